// round 6
// baseline (speedup 1.0000x reference)
#include <cuda_runtime.h>
#include <cstdint>

#define NN 50000
#define EE 625000
#define FF 128
#define GG 64
#define GN_EPS 1e-5f

// ---------------- scratch (static device globals; no allocs) ----------------
__device__ __align__(16) float d_deg[NN];
__device__ __align__(16) float d_dinv[NN];
__device__ __align__(16) int   d_cnt[NN];
__device__ __align__(16) int   d_rowptr[NN + 1];
__device__ __align__(16) int   d_cursor[NN];
__device__ __align__(16) int   d_col[EE];
__device__ __align__(16) float d_val[EE];
__device__ __align__(16) float d_hbuf[3 * NN * FF];     // h1, h2, h3
__device__ __align__(16) float d_gmean[GG * FF];
__device__ __align__(16) float d_grvar[GG * FF];
__device__ __align__(16) int   d_gstart[GG + 1];

// ---------------- kernels ----------------

__global__ void zero_kernel() {
    int i = blockIdx.x * blockDim.x + threadIdx.x;
    if (i < NN) { d_deg[i] = 0.f; d_cnt[i] = 0; }
}

// edge_index is int32 on device (JAX default x64-disabled demotes int64->int32)
__global__ void deg_kernel(const int* __restrict__ ei,
                           const float* __restrict__ ew) {
    int e = blockIdx.x * blockDim.x + threadIdx.x;
    if (e >= EE) return;
    int dst = ei[EE + e];
    atomicAdd(&d_deg[dst], ew[e]);
    atomicAdd(&d_cnt[dst], 1);
}

__global__ void dinv_kernel() {
    int i = blockIdx.x * blockDim.x + threadIdx.x;
    if (i >= NN) return;
    float d = d_deg[i];
    d_dinv[i] = (d > 0.f) ? rsqrtf(fmaxf(d, 1e-30f)) : 0.f;
}

// single-block exclusive scan of d_cnt -> d_rowptr / d_cursor
__global__ void scan_kernel() {
    __shared__ int wsum[32];
    __shared__ int carry;
    if (threadIdx.x == 0) carry = 0;
    __syncthreads();
    int lane = threadIdx.x & 31;
    int wid  = threadIdx.x >> 5;
    for (int base = 0; base < NN; base += 1024) {
        int i = base + threadIdx.x;
        int x = (i < NN) ? d_cnt[i] : 0;
        int v = x;
        #pragma unroll
        for (int o = 1; o < 32; o <<= 1) {
            int t = __shfl_up_sync(0xFFFFFFFFu, v, o);
            if (lane >= o) v += t;
        }
        if (lane == 31) wsum[wid] = v;
        __syncthreads();
        if (threadIdx.x < 32) {
            int t = wsum[threadIdx.x];
            #pragma unroll
            for (int o = 1; o < 32; o <<= 1) {
                int u = __shfl_up_sync(0xFFFFFFFFu, t, o);
                if (threadIdx.x >= o) t += u;
            }
            wsum[threadIdx.x] = t;
        }
        __syncthreads();
        int incl = v + (wid > 0 ? wsum[wid - 1] : 0);
        int c = carry;
        if (i < NN) {
            int excl = c + incl - x;
            d_rowptr[i] = excl;
            d_cursor[i] = excl;
        }
        __syncthreads();
        if (threadIdx.x == 1023) carry = c + incl;
        __syncthreads();
    }
    if (threadIdx.x == 0) d_rowptr[NN] = carry;
}

__global__ void fill_kernel(const int* __restrict__ ei,
                            const float* __restrict__ ew) {
    int e = blockIdx.x * blockDim.x + threadIdx.x;
    if (e >= EE) return;
    int s = ei[e];
    int d = ei[EE + e];
    float nv = d_dinv[s] * ew[e] * d_dinv[d];
    int p = atomicAdd(&d_cursor[d], 1);
    d_col[p] = s;
    d_val[p] = nv;
}

// one warp per destination row, float4 per lane (128 feats).
// in_idx < 0  -> read from y; else read from d_hbuf[in_idx].
// Buffer selection happens DEVICE-side (no host symbol resolution).
__global__ void spmm_kernel(const float* __restrict__ y,
                            int in_idx, int out_idx) {
    const float* hin = (in_idx < 0) ? y : (d_hbuf + (size_t)in_idx * NN * FF);
    float* hout = d_hbuf + (size_t)out_idx * NN * FF;
    int warp = (blockIdx.x * blockDim.x + threadIdx.x) >> 5;
    if (warp >= NN) return;
    int lane = threadIdx.x & 31;
    int beg = d_rowptr[warp], end = d_rowptr[warp + 1];
    float4 acc = make_float4(0.f, 0.f, 0.f, 0.f);
    int e = beg;
    // unroll-8: batch 8 independent gathers -> deeper MLP against L2 latency
    for (; e + 8 <= end; e += 8) {
        int c[8]; float v[8];
        #pragma unroll
        for (int u = 0; u < 8; ++u) { c[u] = d_col[e + u]; v[u] = d_val[e + u]; }
        float4 x[8];
        #pragma unroll
        for (int u = 0; u < 8; ++u)
            x[u] = *(const float4*)&hin[(size_t)c[u] * FF + lane * 4];
        #pragma unroll
        for (int u = 0; u < 8; ++u) {
            acc.x += v[u] * x[u].x;
            acc.y += v[u] * x[u].y;
            acc.z += v[u] * x[u].z;
            acc.w += v[u] * x[u].w;
        }
    }
    for (; e + 4 <= end; e += 4) {
        int   c0 = d_col[e],   c1 = d_col[e+1], c2 = d_col[e+2], c3 = d_col[e+3];
        float v0 = d_val[e],   v1 = d_val[e+1], v2 = d_val[e+2], v3 = d_val[e+3];
        float4 x0 = *(const float4*)&hin[(size_t)c0 * FF + lane * 4];
        float4 x1 = *(const float4*)&hin[(size_t)c1 * FF + lane * 4];
        float4 x2 = *(const float4*)&hin[(size_t)c2 * FF + lane * 4];
        float4 x3 = *(const float4*)&hin[(size_t)c3 * FF + lane * 4];
        acc.x += v0*x0.x + v1*x1.x + v2*x2.x + v3*x3.x;
        acc.y += v0*x0.y + v1*x1.y + v2*x2.y + v3*x3.y;
        acc.z += v0*x0.z + v1*x1.z + v2*x2.z + v3*x3.z;
        acc.w += v0*x0.w + v1*x1.w + v2*x2.w + v3*x3.w;
    }
    for (; e < end; ++e) {
        int c = d_col[e]; float v = d_val[e];
        float4 x = *(const float4*)&hin[(size_t)c * FF + lane * 4];
        acc.x += v*x.x; acc.y += v*x.y; acc.z += v*x.z; acc.w += v*x.w;
    }
    *(float4*)&hout[(size_t)warp * FF + lane * 4] = acc;
}

// out[N,128] = sum_{p=0..3} A_p[N,128] @ W_p[128,128] + b
// block: 64 rows x 128 cols, 256 threads, each thread 4x8 outputs
__global__ void gemm_kernel(const float* __restrict__ y,
                            const float* __restrict__ tag_w,
                            const float* __restrict__ tag_b,
                            float* __restrict__ out) {
    __shared__ __align__(16) float As[16][64];
    __shared__ __align__(16) float Bs[16][128];
    int block_row = blockIdx.x * 64;
    int tid = threadIdx.x;
    int tx = tid & 15;   // col group (8 cols each)
    int ty = tid >> 4;   // row group (4 rows each)
    float acc[4][8];
    #pragma unroll
    for (int i = 0; i < 4; ++i)
        #pragma unroll
        for (int j = 0; j < 8; ++j) acc[i][j] = 0.f;

    for (int p = 0; p < 4; ++p) {
        const float* A = (p == 0) ? y : (d_hbuf + (size_t)(p - 1) * NN * FF);
        const float* W = tag_w + p * FF * FF;
        for (int k0 = 0; k0 < FF; k0 += 16) {
            // A tile 64x16 (store transposed)
            {
                int r  = tid >> 2;        // 0..63
                int c4 = (tid & 3) * 4;   // 0,4,8,12
                int grow = block_row + r;
                float4 a = make_float4(0.f, 0.f, 0.f, 0.f);
                if (grow < NN) a = *(const float4*)&A[(size_t)grow * FF + k0 + c4];
                As[c4 + 0][r] = a.x; As[c4 + 1][r] = a.y;
                As[c4 + 2][r] = a.z; As[c4 + 3][r] = a.w;
            }
            // B tile 16x128
            {
                int r = tid >> 4;         // 0..15
                int c = (tid & 15) * 8;   // 0..120
                const float* src = &W[(k0 + r) * FF + c];
                *(float4*)&Bs[r][c]     = *(const float4*)src;
                *(float4*)&Bs[r][c + 4] = *(const float4*)(src + 4);
            }
            __syncthreads();
            #pragma unroll
            for (int kk = 0; kk < 16; ++kk) {
                float4 af = *(float4*)&As[kk][ty * 4];
                float4 b0 = *(float4*)&Bs[kk][tx * 8];
                float4 b1 = *(float4*)&Bs[kk][tx * 8 + 4];
                float av[4] = {af.x, af.y, af.z, af.w};
                float bv[8] = {b0.x, b0.y, b0.z, b0.w, b1.x, b1.y, b1.z, b1.w};
                #pragma unroll
                for (int i = 0; i < 4; ++i)
                    #pragma unroll
                    for (int j = 0; j < 8; ++j)
                        acc[i][j] += av[i] * bv[j];
            }
            __syncthreads();
        }
    }
    // epilogue: + bias
    float bsv[8];
    #pragma unroll
    for (int j = 0; j < 8; ++j) bsv[j] = tag_b[tx * 8 + j];
    #pragma unroll
    for (int i = 0; i < 4; ++i) {
        int grow = block_row + ty * 4 + i;
        if (grow < NN) {
            float4 o0 = make_float4(acc[i][0] + bsv[0], acc[i][1] + bsv[1],
                                    acc[i][2] + bsv[2], acc[i][3] + bsv[3]);
            float4 o1 = make_float4(acc[i][4] + bsv[4], acc[i][5] + bsv[5],
                                    acc[i][6] + bsv[6], acc[i][7] + bsv[7]);
            *(float4*)&out[(size_t)grow * FF + tx * 8]     = o0;
            *(float4*)&out[(size_t)grow * FF + tx * 8 + 4] = o1;
        }
    }
}

// graph segment boundaries (batch is sorted, int32)
__global__ void bounds_kernel(const int* __restrict__ batch) {
    int n = blockIdx.x * blockDim.x + threadIdx.x;
    if (n >= NN) return;
    int b  = batch[n];
    int bp = (n == 0) ? -1 : batch[n - 1];
    for (int g = bp + 1; g <= b; ++g) d_gstart[g] = n;
    if (n == NN - 1)
        for (int g = b + 1; g <= GG; ++g) d_gstart[g] = NN;
}

// per-graph mean / rsqrt(var+eps); one block per graph, one thread per feature
__global__ void stats_kernel(const float* __restrict__ out,
                             const float* __restrict__ gn_mean_scale) {
    int g = blockIdx.x;
    int f = threadIdx.x;
    int s0 = d_gstart[g], s1 = d_gstart[g + 1];
    float sum = 0.f, sq = 0.f;
    int n = s0;
    for (; n + 4 <= s1; n += 4) {
        float v0 = out[(size_t)(n + 0) * FF + f];
        float v1 = out[(size_t)(n + 1) * FF + f];
        float v2 = out[(size_t)(n + 2) * FF + f];
        float v3 = out[(size_t)(n + 3) * FF + f];
        sum += v0 + v1 + v2 + v3;
        sq  += v0*v0 + v1*v1 + v2*v2 + v3*v3;
    }
    for (; n < s1; ++n) {
        float v = out[(size_t)n * FF + f];
        sum += v; sq += v * v;
    }
    float cnt = (float)max(s1 - s0, 1);
    float mean = sum / cnt;
    float msq  = sq / cnt;
    float sc = gn_mean_scale[f];
    // E[(x - sc*mean)^2] = E[x^2] - 2*sc*mean*E[x] + sc^2*mean^2
    float var = msq - 2.f * sc * mean * mean + sc * sc * mean * mean;
    d_gmean[g * FF + f] = mean;
    d_grvar[g * FF + f] = rsqrtf(var + GN_EPS);
}

// in-place: out = y + relu(gn_w * (out - s*mean) * rvar + gn_b)
__global__ void final_kernel(const float* __restrict__ y,
                             const int* __restrict__ batch,
                             const float* __restrict__ gn_weight,
                             const float* __restrict__ gn_bias,
                             const float* __restrict__ gn_mean_scale,
                             float* __restrict__ out) {
    int idx = blockIdx.x * blockDim.x + threadIdx.x;   // N*32
    if (idx >= NN * 32) return;
    int n = idx >> 5;
    int f = (idx & 31) * 4;
    int g = batch[n];
    float4 o = *(float4*)&out[(size_t)n * FF + f];
    float4 m = *(const float4*)&d_gmean[g * FF + f];
    float4 r = *(const float4*)&d_grvar[g * FF + f];
    float4 w = *(const float4*)&gn_weight[f];
    float4 b = *(const float4*)&gn_bias[f];
    float4 s = *(const float4*)&gn_mean_scale[f];
    float4 yy = *(const float4*)&y[(size_t)n * FF + f];
    float4 res;
    res.x = yy.x + fmaxf(w.x * (o.x - s.x * m.x) * r.x + b.x, 0.f);
    res.y = yy.y + fmaxf(w.y * (o.y - s.y * m.y) * r.y + b.y, 0.f);
    res.z = yy.z + fmaxf(w.z * (o.z - s.z * m.z) * r.z + b.z, 0.f);
    res.w = yy.w + fmaxf(w.w * (o.w - s.w * m.w) * r.w + b.w, 0.f);
    *(float4*)&out[(size_t)n * FF + f] = res;
}

// ---------------- launch ----------------
extern "C" void kernel_launch(void* const* d_in, const int* in_sizes, int n_in,
                              void* d_out, int out_size) {
    const float* y     = (const float*)d_in[0];
    const int*   ei    = (const int*)d_in[1];     // int32 (JAX x64-disabled)
    const float* ew    = (const float*)d_in[2];
    const int*   batch = (const int*)d_in[3];     // int32
    const float* tag_w = (const float*)d_in[4];
    const float* tag_b = (const float*)d_in[5];
    const float* gn_w  = (const float*)d_in[6];
    const float* gn_b  = (const float*)d_in[7];
    const float* gn_ms = (const float*)d_in[8];
    float* out = (float*)d_out;

    const int TB = 256;
    const int gN  = (NN + TB - 1) / TB;
    const int gE  = (EE + TB - 1) / TB;
    const int gW  = (NN * 32 + TB - 1) / TB;   // warp-per-row kernels

    zero_kernel<<<gN, TB>>>();
    deg_kernel<<<gE, TB>>>(ei, ew);
    dinv_kernel<<<gN, TB>>>();
    scan_kernel<<<1, 1024>>>();
    fill_kernel<<<gE, TB>>>(ei, ew);
    bounds_kernel<<<gN, TB>>>(batch);

    spmm_kernel<<<gW, TB>>>(y, -1, 0);   // y  -> h1
    spmm_kernel<<<gW, TB>>>(y,  0, 1);   // h1 -> h2
    spmm_kernel<<<gW, TB>>>(y,  1, 2);   // h2 -> h3

    gemm_kernel<<<(NN + 63) / 64, 256>>>(y, tag_w, tag_b, out);

    stats_kernel<<<GG, FF>>>(out, gn_ms);
    final_kernel<<<gW, TB>>>(y, batch, gn_w, gn_b, gn_ms, out);
}

// round 8
// speedup vs baseline: 1.6098x; 1.6098x over previous
#include <cuda_runtime.h>
#include <cstdint>

#define NN 50000
#define EE 625000
#define FF 128
#define GG 64
#define GN_EPS 1e-5f
#define NBLK 196   // ceil(NN/256)

// ---------------- scratch (static device globals; no allocs) ----------------
__device__ __align__(16) float d_deg[NN];
__device__ __align__(16) float d_dinv[NN];
__device__ __align__(16) int   d_cnt[NN];
__device__ __align__(16) int   d_rowptr[NN + 1];
__device__ __align__(16) int   d_cursor[NN];
__device__ __align__(16) int   d_bsum[256];
__device__ __align__(16) int   d_col[EE];
__device__ __align__(16) float d_val[EE];
__device__ __align__(16) float d_hbuf[3 * NN * FF];     // h1, h2, h3
__device__ __align__(16) float d_gmean[GG * FF];
__device__ __align__(16) float d_grvar[GG * FF];
__device__ __align__(16) int   d_gstart[GG + 1];

#define FFMA2(d, a, b, c) \
    asm("fma.rn.f32x2 %0, %1, %2, %3;" : "=l"(d) : "l"(a), "l"(b), "l"(c))

// ---------------- prep kernels ----------------

__global__ void zero_kernel() {
    int i = blockIdx.x * blockDim.x + threadIdx.x;
    if (i < NN) { d_deg[i] = 0.f; d_cnt[i] = 0; }
}

__global__ void deg_kernel(const int* __restrict__ ei,
                           const float* __restrict__ ew) {
    int e = blockIdx.x * blockDim.x + threadIdx.x;
    if (e >= EE) return;
    int dst = ei[EE + e];
    atomicAdd(&d_deg[dst], ew[e]);
    atomicAdd(&d_cnt[dst], 1);
}

__global__ void dinv_kernel() {
    int i = blockIdx.x * blockDim.x + threadIdx.x;
    if (i >= NN) return;
    float d = d_deg[i];
    d_dinv[i] = (d > 0.f) ? rsqrtf(fmaxf(d, 1e-30f)) : 0.f;
}

// ---- parallel 3-phase exclusive scan of d_cnt -> d_rowptr/d_cursor ----
__device__ __forceinline__ int warp_incl_scan(int v, int lane) {
    #pragma unroll
    for (int o = 1; o < 32; o <<= 1) {
        int t = __shfl_up_sync(0xFFFFFFFFu, v, o);
        if (lane >= o) v += t;
    }
    return v;
}

__global__ void scan_block_kernel() {
    __shared__ int ws[8];
    int t = threadIdx.x, b = blockIdx.x;
    int i = b * 256 + t;
    int lane = t & 31, wid = t >> 5;
    int x = (i < NN) ? d_cnt[i] : 0;
    int v = warp_incl_scan(x, lane);
    if (lane == 31) ws[wid] = v;
    __syncthreads();
    if (t == 0) {
        int s = 0;
        #pragma unroll
        for (int k = 0; k < 8; ++k) { int tmp = ws[k]; ws[k] = s; s += tmp; }
    }
    __syncthreads();
    int excl = v - x + ws[wid];
    if (i < NN) d_rowptr[i] = excl;          // block-local for now
    if (t == 255) d_bsum[b] = excl + x;      // block total
}

__global__ void scan_sums_kernel() {
    __shared__ int ws[8];
    int t = threadIdx.x;
    int lane = t & 31, wid = t >> 5;
    int x = (t < NBLK) ? d_bsum[t] : 0;
    int v = warp_incl_scan(x, lane);
    if (lane == 31) ws[wid] = v;
    __syncthreads();
    if (t == 0) {
        int s = 0;
        #pragma unroll
        for (int k = 0; k < 8; ++k) { int tmp = ws[k]; ws[k] = s; s += tmp; }
    }
    __syncthreads();
    int excl = v - x + ws[wid];
    if (t < NBLK) d_bsum[t] = excl;
    if (t == NBLK - 1) d_rowptr[NN] = excl + x;   // = EE
}

__global__ void scan_add_kernel() {
    int i = blockIdx.x * 256 + threadIdx.x;
    if (i >= NN) return;
    int r = d_rowptr[i] + d_bsum[blockIdx.x];
    d_rowptr[i] = r;
    d_cursor[i] = r;
}

__global__ void fill_kernel(const int* __restrict__ ei,
                            const float* __restrict__ ew) {
    int e = blockIdx.x * blockDim.x + threadIdx.x;
    if (e >= EE) return;
    int s = ei[e];
    int d = ei[EE + e];
    float nv = d_dinv[s] * ew[e] * d_dinv[d];
    int p = atomicAdd(&d_cursor[d], 1);
    d_col[p] = s;
    d_val[p] = nv;
}

// ---------------- SpMM: one warp per destination row ----------------
__global__ void spmm_kernel(const float* __restrict__ y,
                            int in_idx, int out_idx) {
    const float* hin = (in_idx < 0) ? y : (d_hbuf + (size_t)in_idx * NN * FF);
    float* hout = d_hbuf + (size_t)out_idx * NN * FF;
    int warp = (blockIdx.x * blockDim.x + threadIdx.x) >> 5;
    if (warp >= NN) return;
    int lane = threadIdx.x & 31;
    int beg = d_rowptr[warp], end = d_rowptr[warp + 1];
    float4 acc = make_float4(0.f, 0.f, 0.f, 0.f);
    int e = beg;
    for (; e + 8 <= end; e += 8) {
        int c[8]; float v[8];
        #pragma unroll
        for (int u = 0; u < 8; ++u) { c[u] = d_col[e + u]; v[u] = d_val[e + u]; }
        float4 x[8];
        #pragma unroll
        for (int u = 0; u < 8; ++u)
            x[u] = *(const float4*)&hin[(size_t)c[u] * FF + lane * 4];
        #pragma unroll
        for (int u = 0; u < 8; ++u) {
            acc.x += v[u] * x[u].x;
            acc.y += v[u] * x[u].y;
            acc.z += v[u] * x[u].z;
            acc.w += v[u] * x[u].w;
        }
    }
    for (; e + 4 <= end; e += 4) {
        int   c0 = d_col[e],   c1 = d_col[e+1], c2 = d_col[e+2], c3 = d_col[e+3];
        float v0 = d_val[e],   v1 = d_val[e+1], v2 = d_val[e+2], v3 = d_val[e+3];
        float4 x0 = *(const float4*)&hin[(size_t)c0 * FF + lane * 4];
        float4 x1 = *(const float4*)&hin[(size_t)c1 * FF + lane * 4];
        float4 x2 = *(const float4*)&hin[(size_t)c2 * FF + lane * 4];
        float4 x3 = *(const float4*)&hin[(size_t)c3 * FF + lane * 4];
        acc.x += v0*x0.x + v1*x1.x + v2*x2.x + v3*x3.x;
        acc.y += v0*x0.y + v1*x1.y + v2*x2.y + v3*x3.y;
        acc.z += v0*x0.z + v1*x1.z + v2*x2.z + v3*x3.z;
        acc.w += v0*x0.w + v1*x1.w + v2*x2.w + v3*x3.w;
    }
    for (; e < end; ++e) {
        int c = d_col[e]; float v = d_val[e];
        float4 x = *(const float4*)&hin[(size_t)c * FF + lane * 4];
        acc.x += v*x.x; acc.y += v*x.y; acc.z += v*x.z; acc.w += v*x.w;
    }
    *(float4*)&hout[(size_t)warp * FF + lane * 4] = acc;
}

// ---------------- GEMM with packed f32x2 FMA ----------------
// out[N,128] = sum_{p=0..3} A_p[N,128] @ W_p[128,128] + b
// block tile 128x128, 256 threads, each thread 8 rows x 8 cols
// (cols held as 4 f32x2 pairs per row)
__global__ __launch_bounds__(256) void gemm_kernel(
        const float* __restrict__ y,
        const float* __restrict__ tag_w,
        const float* __restrict__ tag_b,
        float* __restrict__ out) {
    __shared__ __align__(16) float As[16][128];   // [k][row]
    __shared__ __align__(16) float Bs[16][128];   // [k][col]
    int block_row = blockIdx.x * 128;
    int tid = threadIdx.x;
    int tx = tid & 15;    // col group: 8 cols
    int ty = tid >> 4;    // row group: 8 rows
    unsigned long long acc2[8][4];
    #pragma unroll
    for (int i = 0; i < 8; ++i)
        #pragma unroll
        for (int j = 0; j < 4; ++j) acc2[i][j] = 0ull;

    for (int p = 0; p < 4; ++p) {
        const float* A = (p == 0) ? y : (d_hbuf + (size_t)(p - 1) * NN * FF);
        const float* W = tag_w + p * FF * FF;
        for (int k0 = 0; k0 < FF; k0 += 16) {
            // A tile: 128 rows x 16 k, store transposed As[k][row]
            #pragma unroll
            for (int q = 0; q < 2; ++q) {
                int idx = tid + q * 256;      // 0..511
                int r  = idx >> 2;            // 0..127
                int c4 = (idx & 3) * 4;       // 0,4,8,12
                int grow = block_row + r;
                float4 a = make_float4(0.f, 0.f, 0.f, 0.f);
                if (grow < NN) a = *(const float4*)&A[(size_t)grow * FF + k0 + c4];
                As[c4 + 0][r] = a.x; As[c4 + 1][r] = a.y;
                As[c4 + 2][r] = a.z; As[c4 + 3][r] = a.w;
            }
            // B tile: 16 k x 128 cols
            #pragma unroll
            for (int q = 0; q < 2; ++q) {
                int idx = tid + q * 256;      // 0..511
                int r = idx >> 5;             // 0..15
                int c = (idx & 31) * 4;       // 0..124
                *(float4*)&Bs[r][c] = *(const float4*)&W[(k0 + r) * FF + c];
            }
            __syncthreads();
            #pragma unroll
            for (int kk = 0; kk < 16; ++kk) {
                float4 af0 = *(float4*)&As[kk][ty * 8];
                float4 af1 = *(float4*)&As[kk][ty * 8 + 4];
                ulonglong2 bb01 = *(ulonglong2*)&Bs[kk][tx * 8];
                ulonglong2 bb23 = *(ulonglong2*)&Bs[kk][tx * 8 + 4];
                unsigned long long bb[4] = {bb01.x, bb01.y, bb23.x, bb23.y};
                float av[8] = {af0.x, af0.y, af0.z, af0.w,
                               af1.x, af1.y, af1.z, af1.w};
                #pragma unroll
                for (int i = 0; i < 8; ++i) {
                    unsigned int au = __float_as_uint(av[i]);
                    unsigned long long aa;
                    asm("mov.b64 %0, {%1, %1};" : "=l"(aa) : "r"(au));
                    #pragma unroll
                    for (int j = 0; j < 4; ++j)
                        FFMA2(acc2[i][j], aa, bb[j], acc2[i][j]);
                }
            }
            __syncthreads();
        }
    }
    // epilogue: unpack, add bias, store
    float bsv[8];
    #pragma unroll
    for (int j = 0; j < 8; ++j) bsv[j] = tag_b[tx * 8 + j];
    #pragma unroll
    for (int i = 0; i < 8; ++i) {
        int grow = block_row + ty * 8 + i;
        if (grow < NN) {
            float o[8];
            #pragma unroll
            for (int j = 0; j < 4; ++j) {
                unsigned int lo, hi;
                asm("mov.b64 {%0, %1}, %2;" : "=r"(lo), "=r"(hi) : "l"(acc2[i][j]));
                o[2*j]   = __uint_as_float(lo) + bsv[2*j];
                o[2*j+1] = __uint_as_float(hi) + bsv[2*j+1];
            }
            *(float4*)&out[(size_t)grow * FF + tx * 8] =
                make_float4(o[0], o[1], o[2], o[3]);
            *(float4*)&out[(size_t)grow * FF + tx * 8 + 4] =
                make_float4(o[4], o[5], o[6], o[7]);
        }
    }
}

// graph segment boundaries (batch is sorted, int32)
__global__ void bounds_kernel(const int* __restrict__ batch) {
    int n = blockIdx.x * blockDim.x + threadIdx.x;
    if (n >= NN) return;
    int b  = batch[n];
    int bp = (n == 0) ? -1 : batch[n - 1];
    for (int g = bp + 1; g <= b; ++g) d_gstart[g] = n;
    if (n == NN - 1)
        for (int g = b + 1; g <= GG; ++g) d_gstart[g] = NN;
}

// per-graph mean / rsqrt(var+eps); one block per graph, 512 threads
// (4 row-lanes x 128 features)
__global__ void stats_kernel(const float* __restrict__ out,
                             const float* __restrict__ gn_mean_scale) {
    __shared__ float ssum[4][FF];
    __shared__ float ssq[4][FF];
    int g  = blockIdx.x;
    int f  = threadIdx.x & 127;
    int rr = threadIdx.x >> 7;     // 0..3
    int s0 = d_gstart[g], s1 = d_gstart[g + 1];
    float sum = 0.f, sq = 0.f;
    for (int n = s0 + rr; n < s1; n += 4) {
        float v = out[(size_t)n * FF + f];
        sum += v; sq += v * v;
    }
    ssum[rr][f] = sum; ssq[rr][f] = sq;
    __syncthreads();
    if (threadIdx.x < FF) {
        sum = ssum[0][f] + ssum[1][f] + ssum[2][f] + ssum[3][f];
        sq  = ssq[0][f]  + ssq[1][f]  + ssq[2][f]  + ssq[3][f];
        float cnt = (float)max(s1 - s0, 1);
        float mean = sum / cnt;
        float msq  = sq / cnt;
        float sc = gn_mean_scale[f];
        // E[(x - sc*mean)^2] = E[x^2] - 2*sc*mean^2 + sc^2*mean^2
        float var = msq - 2.f * sc * mean * mean + sc * sc * mean * mean;
        d_gmean[g * FF + f] = mean;
        d_grvar[g * FF + f] = rsqrtf(var + GN_EPS);
    }
}

// in-place: out = y + relu(gn_w * (out - s*mean) * rvar + gn_b)
__global__ void final_kernel(const float* __restrict__ y,
                             const int* __restrict__ batch,
                             const float* __restrict__ gn_weight,
                             const float* __restrict__ gn_bias,
                             const float* __restrict__ gn_mean_scale,
                             float* __restrict__ out) {
    int idx = blockIdx.x * blockDim.x + threadIdx.x;   // N*32
    if (idx >= NN * 32) return;
    int n = idx >> 5;
    int f = (idx & 31) * 4;
    int g = batch[n];
    float4 o = *(float4*)&out[(size_t)n * FF + f];
    float4 m = *(const float4*)&d_gmean[g * FF + f];
    float4 r = *(const float4*)&d_grvar[g * FF + f];
    float4 w = *(const float4*)&gn_weight[f];
    float4 b = *(const float4*)&gn_bias[f];
    float4 s = *(const float4*)&gn_mean_scale[f];
    float4 yy = *(const float4*)&y[(size_t)n * FF + f];
    float4 res;
    res.x = yy.x + fmaxf(w.x * (o.x - s.x * m.x) * r.x + b.x, 0.f);
    res.y = yy.y + fmaxf(w.y * (o.y - s.y * m.y) * r.y + b.y, 0.f);
    res.z = yy.z + fmaxf(w.z * (o.z - s.z * m.z) * r.z + b.z, 0.f);
    res.w = yy.w + fmaxf(w.w * (o.w - s.w * m.w) * r.w + b.w, 0.f);
    *(float4*)&out[(size_t)n * FF + f] = res;
}

// ---------------- launch ----------------
extern "C" void kernel_launch(void* const* d_in, const int* in_sizes, int n_in,
                              void* d_out, int out_size) {
    const float* y     = (const float*)d_in[0];
    const int*   ei    = (const int*)d_in[1];     // int32 (JAX x64-disabled)
    const float* ew    = (const float*)d_in[2];
    const int*   batch = (const int*)d_in[3];     // int32
    const float* tag_w = (const float*)d_in[4];
    const float* tag_b = (const float*)d_in[5];
    const float* gn_w  = (const float*)d_in[6];
    const float* gn_b  = (const float*)d_in[7];
    const float* gn_ms = (const float*)d_in[8];
    float* out = (float*)d_out;

    const int TB = 256;
    const int gN  = (NN + TB - 1) / TB;
    const int gE  = (EE + TB - 1) / TB;
    const int gW  = (NN * 32 + TB - 1) / TB;   // warp-per-row kernels

    zero_kernel<<<gN, TB>>>();
    deg_kernel<<<gE, TB>>>(ei, ew);
    dinv_kernel<<<gN, TB>>>();
    scan_block_kernel<<<NBLK, 256>>>();
    scan_sums_kernel<<<1, 256>>>();
    scan_add_kernel<<<NBLK, 256>>>();
    fill_kernel<<<gE, TB>>>(ei, ew);
    bounds_kernel<<<gN, TB>>>(batch);

    spmm_kernel<<<gW, TB>>>(y, -1, 0);   // y  -> h1
    spmm_kernel<<<gW, TB>>>(y,  0, 1);   // h1 -> h2
    spmm_kernel<<<gW, TB>>>(y,  1, 2);   // h2 -> h3

    gemm_kernel<<<(NN + 127) / 128, 256>>>(y, tag_w, tag_b, out);

    stats_kernel<<<GG, 512>>>(out, gn_ms);
    final_kernel<<<gW, TB>>>(y, batch, gn_w, gn_b, gn_ms, out);
}

// round 12
// speedup vs baseline: 1.7012x; 1.0568x over previous
#include <cuda_runtime.h>
#include <cstdint>

#define NN 50000
#define EE 625000
#define FF 128
#define GG 64
#define GN_EPS 1e-5f
#define NBLK 196   // ceil(NN/256)
#define STR 33     // smem tile stride (floats)

// ---------------- scratch (static device globals; no allocs) ----------------
__device__ __align__(16) float d_deg[NN];
__device__ __align__(16) float d_dinv[NN];
__device__ __align__(16) int   d_cnt[NN];
__device__ __align__(16) int   d_rowptr[NN + 1];
__device__ __align__(16) int   d_cursor[NN];
__device__ __align__(16) int   d_bsum[256];
__device__ __align__(16) int   d_col[EE];
__device__ __align__(16) float d_val[EE];
__device__ __align__(16) float d_hbuf[3 * NN * FF];     // h1, h2, h3
__device__ __align__(16) float d_wt[4 * FF * FF];       // W^T per hop
__device__ __align__(16) float d_gmean[GG * FF];
__device__ __align__(16) float d_grvar[GG * FF];
__device__ __align__(16) int   d_gstart[GG + 1];

__device__ __forceinline__ uint32_t f2tf32(float f) {
    uint32_t u;
    asm("cvt.rna.tf32.f32 %0, %1;" : "=r"(u) : "f"(f));
    return u;
}

__device__ __forceinline__ void mma_tf32(float* c, const uint32_t* a,
                                         const uint32_t* b) {
    asm volatile(
        "mma.sync.aligned.m16n8k8.row.col.f32.tf32.tf32.f32 "
        "{%0,%1,%2,%3}, {%4,%5,%6,%7}, {%8,%9}, {%0,%1,%2,%3};"
        : "+f"(c[0]), "+f"(c[1]), "+f"(c[2]), "+f"(c[3])
        : "r"(a[0]), "r"(a[1]), "r"(a[2]), "r"(a[3]), "r"(b[0]), "r"(b[1]));
}

// ---------------- prep kernels ----------------

__global__ void zero_kernel() {
    int i = blockIdx.x * blockDim.x + threadIdx.x;
    if (i < NN) { d_deg[i] = 0.f; d_cnt[i] = 0; }
}

__global__ void deg_kernel(const int* __restrict__ ei,
                           const float* __restrict__ ew) {
    int e = blockIdx.x * blockDim.x + threadIdx.x;
    if (e >= EE) return;
    int dst = ei[EE + e];
    atomicAdd(&d_deg[dst], ew[e]);
    atomicAdd(&d_cnt[dst], 1);
}

__global__ void dinv_kernel() {
    int i = blockIdx.x * blockDim.x + threadIdx.x;
    if (i >= NN) return;
    float d = d_deg[i];
    d_dinv[i] = (d > 0.f) ? rsqrtf(fmaxf(d, 1e-30f)) : 0.f;
}

__device__ __forceinline__ int warp_incl_scan(int v, int lane) {
    #pragma unroll
    for (int o = 1; o < 32; o <<= 1) {
        int t = __shfl_up_sync(0xFFFFFFFFu, v, o);
        if (lane >= o) v += t;
    }
    return v;
}

__global__ void scan_block_kernel() {
    __shared__ int ws[8];
    int t = threadIdx.x, b = blockIdx.x;
    int i = b * 256 + t;
    int lane = t & 31, wid = t >> 5;
    int x = (i < NN) ? d_cnt[i] : 0;
    int v = warp_incl_scan(x, lane);
    if (lane == 31) ws[wid] = v;
    __syncthreads();
    if (t == 0) {
        int s = 0;
        #pragma unroll
        for (int k = 0; k < 8; ++k) { int tmp = ws[k]; ws[k] = s; s += tmp; }
    }
    __syncthreads();
    int excl = v - x + ws[wid];
    if (i < NN) d_rowptr[i] = excl;
    if (t == 255) d_bsum[b] = excl + x;
}

__global__ void scan_sums_kernel() {
    __shared__ int ws[8];
    int t = threadIdx.x;
    int lane = t & 31, wid = t >> 5;
    int x = (t < NBLK) ? d_bsum[t] : 0;
    int v = warp_incl_scan(x, lane);
    if (lane == 31) ws[wid] = v;
    __syncthreads();
    if (t == 0) {
        int s = 0;
        #pragma unroll
        for (int k = 0; k < 8; ++k) { int tmp = ws[k]; ws[k] = s; s += tmp; }
    }
    __syncthreads();
    int excl = v - x + ws[wid];
    if (t < NBLK) d_bsum[t] = excl;
    if (t == NBLK - 1) d_rowptr[NN] = excl + x;
}

__global__ void scan_add_kernel() {
    int i = blockIdx.x * 256 + threadIdx.x;
    if (i >= NN) return;
    int r = d_rowptr[i] + d_bsum[blockIdx.x];
    d_rowptr[i] = r;
    d_cursor[i] = r;
}

__global__ void fill_kernel(const int* __restrict__ ei,
                            const float* __restrict__ ew) {
    int e = blockIdx.x * blockDim.x + threadIdx.x;
    if (e >= EE) return;
    int s = ei[e];
    int d = ei[EE + e];
    float nv = d_dinv[s] * ew[e] * d_dinv[d];
    int p = atomicAdd(&d_cursor[d], 1);
    d_col[p] = s;
    d_val[p] = nv;
}

// W^T: d_wt[p][n][k] = tag_w[p][k][n]
__global__ void wtrans_kernel(const float* __restrict__ tag_w) {
    int i = blockIdx.x * 256 + threadIdx.x;
    if (i >= 4 * FF * FF) return;
    int p = i >> 14, rem = i & 16383;
    int n = rem >> 7, k = rem & 127;
    d_wt[i] = tag_w[p * FF * FF + k * FF + n];
}

// ---------------- SpMM: one warp per destination row ----------------
__global__ void spmm_kernel(const float* __restrict__ y,
                            int in_idx, int out_idx) {
    const float* hin = (in_idx < 0) ? y : (d_hbuf + (size_t)in_idx * NN * FF);
    float* hout = d_hbuf + (size_t)out_idx * NN * FF;
    int warp = (blockIdx.x * blockDim.x + threadIdx.x) >> 5;
    if (warp >= NN) return;
    int lane = threadIdx.x & 31;
    int beg = d_rowptr[warp], end = d_rowptr[warp + 1];
    float4 acc = make_float4(0.f, 0.f, 0.f, 0.f);
    int e = beg;
    for (; e + 8 <= end; e += 8) {
        int c[8]; float v[8];
        #pragma unroll
        for (int u = 0; u < 8; ++u) { c[u] = d_col[e + u]; v[u] = d_val[e + u]; }
        float4 x[8];
        #pragma unroll
        for (int u = 0; u < 8; ++u)
            x[u] = *(const float4*)&hin[(size_t)c[u] * FF + lane * 4];
        #pragma unroll
        for (int u = 0; u < 8; ++u) {
            acc.x += v[u] * x[u].x;
            acc.y += v[u] * x[u].y;
            acc.z += v[u] * x[u].z;
            acc.w += v[u] * x[u].w;
        }
    }
    for (; e + 4 <= end; e += 4) {
        int   c0 = d_col[e],   c1 = d_col[e+1], c2 = d_col[e+2], c3 = d_col[e+3];
        float v0 = d_val[e],   v1 = d_val[e+1], v2 = d_val[e+2], v3 = d_val[e+3];
        float4 x0 = *(const float4*)&hin[(size_t)c0 * FF + lane * 4];
        float4 x1 = *(const float4*)&hin[(size_t)c1 * FF + lane * 4];
        float4 x2 = *(const float4*)&hin[(size_t)c2 * FF + lane * 4];
        float4 x3 = *(const float4*)&hin[(size_t)c3 * FF + lane * 4];
        acc.x += v0*x0.x + v1*x1.x + v2*x2.x + v3*x3.x;
        acc.y += v0*x0.y + v1*x1.y + v2*x2.y + v3*x3.y;
        acc.z += v0*x0.z + v1*x1.z + v2*x2.z + v3*x3.z;
        acc.w += v0*x0.w + v1*x1.w + v2*x2.w + v3*x3.w;
    }
    for (; e < end; ++e) {
        int c = d_col[e]; float v = d_val[e];
        float4 x = *(const float4*)&hin[(size_t)c * FF + lane * 4];
        acc.x += v*x.x; acc.y += v*x.y; acc.z += v*x.z; acc.w += v*x.w;
    }
    *(float4*)&hout[(size_t)warp * FF + lane * 4] = acc;
}

// ---------------- tf32 mma.sync GEMM ----------------
// out[N,128] = sum_{p=0..3} A_p[N,128] @ W_p[128,128] + b
// CTA: 128x128 tile, 256 threads (8 warps), warp tile 32x64.
// K=512 in 16 chunks of 32; smem tiles pre-converted to tf32 (cvt.rna).
__global__ __launch_bounds__(256) void gemm_mma_kernel(
        const float* __restrict__ y,
        const float* __restrict__ tag_b,
        float* __restrict__ out) {
    __shared__ uint32_t As[128 * STR];   // [row][k] tf32
    __shared__ uint32_t Bs[128 * STR];   // [n][k]  tf32 (W^T)

    int t = threadIdx.x;
    int wid = t >> 5, lane = t & 31;
    int gid = lane >> 2, tid4 = lane & 3;
    int block_row = blockIdx.x * 128;
    int rbase = (wid >> 1) * 32;         // warp row base (0,32,64,96)
    int cbase = (wid & 1) * 64;          // warp col base (0,64)

    float acc[2][8][4];
    #pragma unroll
    for (int m = 0; m < 2; ++m)
        #pragma unroll
        for (int c = 0; c < 8; ++c)
            #pragma unroll
            for (int j = 0; j < 4; ++j) acc[m][c][j] = 0.f;

    #pragma unroll 1
    for (int chunk = 0; chunk < 16; ++chunk) {
        int p = chunk >> 2, kcc = chunk & 3;
        const float* Asrc = (p == 0) ? y : (d_hbuf + (size_t)(p - 1) * NN * FF);
        const float* Bsrc = d_wt + p * FF * FF;
        __syncthreads();   // previous chunk fully consumed
        // stage A and B chunks (128 rows x 32 k), cvt to tf32 on the fly
        #pragma unroll
        for (int i = 0; i < 4; ++i) {
            int idx = i * 256 + t;        // 0..1023
            int r  = idx >> 3;            // 0..127
            int c4 = (idx & 7) * 4;       // 0..28
            int grow = block_row + r;
            float4 a = make_float4(0.f, 0.f, 0.f, 0.f);
            if (grow < NN)
                a = *(const float4*)&Asrc[(size_t)grow * FF + kcc * 32 + c4];
            As[r * STR + c4 + 0] = f2tf32(a.x);
            As[r * STR + c4 + 1] = f2tf32(a.y);
            As[r * STR + c4 + 2] = f2tf32(a.z);
            As[r * STR + c4 + 3] = f2tf32(a.w);
            float4 b = *(const float4*)&Bsrc[r * FF + kcc * 32 + c4];
            Bs[r * STR + c4 + 0] = f2tf32(b.x);
            Bs[r * STR + c4 + 1] = f2tf32(b.y);
            Bs[r * STR + c4 + 2] = f2tf32(b.z);
            Bs[r * STR + c4 + 3] = f2tf32(b.w);
        }
        __syncthreads();
        // consume: 4 k-steps of 8
        #pragma unroll
        for (int k0 = 0; k0 < 32; k0 += 8) {
            uint32_t a[2][4];
            #pragma unroll
            for (int m = 0; m < 2; ++m) {
                int row = rbase + m * 16 + gid;
                a[m][0] = As[row * STR + k0 + tid4];
                a[m][1] = As[(row + 8) * STR + k0 + tid4];
                a[m][2] = As[row * STR + k0 + tid4 + 4];
                a[m][3] = As[(row + 8) * STR + k0 + tid4 + 4];
            }
            uint32_t b[8][2];
            #pragma unroll
            for (int c = 0; c < 8; ++c) {
                int n = cbase + c * 8 + gid;
                b[c][0] = Bs[n * STR + k0 + tid4];
                b[c][1] = Bs[n * STR + k0 + tid4 + 4];
            }
            #pragma unroll
            for (int m = 0; m < 2; ++m)
                #pragma unroll
                for (int c = 0; c < 8; ++c)
                    mma_tf32(acc[m][c], a[m], b[c]);
        }
    }

    // epilogue: bias + store (c0,c1)->(row, col..col+1), (c2,c3)->(row+8, ..)
    #pragma unroll
    for (int m = 0; m < 2; ++m) {
        int row0 = block_row + rbase + m * 16 + gid;
        #pragma unroll
        for (int c = 0; c < 8; ++c) {
            int col = cbase + c * 8 + 2 * tid4;
            float b0 = tag_b[col], b1 = tag_b[col + 1];
            if (row0 < NN) {
                float2 o = make_float2(acc[m][c][0] + b0, acc[m][c][1] + b1);
                *(float2*)&out[(size_t)row0 * FF + col] = o;
            }
            if (row0 + 8 < NN) {
                float2 o = make_float2(acc[m][c][2] + b0, acc[m][c][3] + b1);
                *(float2*)&out[(size_t)(row0 + 8) * FF + col] = o;
            }
        }
    }
}

// graph segment boundaries (batch is sorted, int32)
__global__ void bounds_kernel(const int* __restrict__ batch) {
    int n = blockIdx.x * blockDim.x + threadIdx.x;
    if (n >= NN) return;
    int b  = batch[n];
    int bp = (n == 0) ? -1 : batch[n - 1];
    for (int g = bp + 1; g <= b; ++g) d_gstart[g] = n;
    if (n == NN - 1)
        for (int g = b + 1; g <= GG; ++g) d_gstart[g] = NN;
}

// per-graph mean / rsqrt(var+eps); one block per graph, 512 threads
__global__ void stats_kernel(const float* __restrict__ out,
                             const float* __restrict__ gn_mean_scale) {
    __shared__ float ssum[4][FF];
    __shared__ float ssq[4][FF];
    int g  = blockIdx.x;
    int f  = threadIdx.x & 127;
    int rr = threadIdx.x >> 7;
    int s0 = d_gstart[g], s1 = d_gstart[g + 1];
    float sum = 0.f, sq = 0.f;
    for (int n = s0 + rr; n < s1; n += 4) {
        float v = out[(size_t)n * FF + f];
        sum += v; sq += v * v;
    }
    ssum[rr][f] = sum; ssq[rr][f] = sq;
    __syncthreads();
    if (threadIdx.x < FF) {
        sum = ssum[0][f] + ssum[1][f] + ssum[2][f] + ssum[3][f];
        sq  = ssq[0][f]  + ssq[1][f]  + ssq[2][f]  + ssq[3][f];
        float cnt = (float)max(s1 - s0, 1);
        float mean = sum / cnt;
        float msq  = sq / cnt;
        float sc = gn_mean_scale[f];
        float var = msq - 2.f * sc * mean * mean + sc * sc * mean * mean;
        d_gmean[g * FF + f] = mean;
        d_grvar[g * FF + f] = rsqrtf(var + GN_EPS);
    }
}

// in-place: out = y + relu(gn_w * (out - s*mean) * rvar + gn_b)
__global__ void final_kernel(const float* __restrict__ y,
                             const int* __restrict__ batch,
                             const float* __restrict__ gn_weight,
                             const float* __restrict__ gn_bias,
                             const float* __restrict__ gn_mean_scale,
                             float* __restrict__ out) {
    int idx = blockIdx.x * blockDim.x + threadIdx.x;   // N*32
    if (idx >= NN * 32) return;
    int n = idx >> 5;
    int f = (idx & 31) * 4;
    int g = batch[n];
    float4 o = *(float4*)&out[(size_t)n * FF + f];
    float4 m = *(const float4*)&d_gmean[g * FF + f];
    float4 r = *(const float4*)&d_grvar[g * FF + f];
    float4 w = *(const float4*)&gn_weight[f];
    float4 b = *(const float4*)&gn_bias[f];
    float4 s = *(const float4*)&gn_mean_scale[f];
    float4 yy = *(const float4*)&y[(size_t)n * FF + f];
    float4 res;
    res.x = yy.x + fmaxf(w.x * (o.x - s.x * m.x) * r.x + b.x, 0.f);
    res.y = yy.y + fmaxf(w.y * (o.y - s.y * m.y) * r.y + b.y, 0.f);
    res.z = yy.z + fmaxf(w.z * (o.z - s.z * m.z) * r.z + b.z, 0.f);
    res.w = yy.w + fmaxf(w.w * (o.w - s.w * m.w) * r.w + b.w, 0.f);
    *(float4*)&out[(size_t)n * FF + f] = res;
}

// ---------------- launch ----------------
extern "C" void kernel_launch(void* const* d_in, const int* in_sizes, int n_in,
                              void* d_out, int out_size) {
    const float* y     = (const float*)d_in[0];
    const int*   ei    = (const int*)d_in[1];     // int32 (JAX x64-disabled)
    const float* ew    = (const float*)d_in[2];
    const int*   batch = (const int*)d_in[3];     // int32
    const float* tag_w = (const float*)d_in[4];
    const float* tag_b = (const float*)d_in[5];
    const float* gn_w  = (const float*)d_in[6];
    const float* gn_b  = (const float*)d_in[7];
    const float* gn_ms = (const float*)d_in[8];
    float* out = (float*)d_out;

    const int TB = 256;
    const int gN  = (NN + TB - 1) / TB;
    const int gE  = (EE + TB - 1) / TB;
    const int gW  = (NN * 32 + TB - 1) / TB;

    zero_kernel<<<gN, TB>>>();
    wtrans_kernel<<<(4 * FF * FF) / 256, 256>>>(tag_w);
    deg_kernel<<<gE, TB>>>(ei, ew);
    dinv_kernel<<<gN, TB>>>();
    scan_block_kernel<<<NBLK, 256>>>();
    scan_sums_kernel<<<1, 256>>>();
    scan_add_kernel<<<NBLK, 256>>>();
    fill_kernel<<<gE, TB>>>(ei, ew);
    bounds_kernel<<<gN, TB>>>(batch);

    spmm_kernel<<<gW, TB>>>(y, -1, 0);   // y  -> h1
    spmm_kernel<<<gW, TB>>>(y,  0, 1);   // h1 -> h2
    spmm_kernel<<<gW, TB>>>(y,  1, 2);   // h2 -> h3

    gemm_mma_kernel<<<(NN + 127) / 128, 256>>>(y, tag_b, out);

    stats_kernel<<<GG, 512>>>(out, gn_ms);
    final_kernel<<<gW, TB>>>(y, batch, gn_w, gn_b, gn_ms, out);
}

// round 13
// speedup vs baseline: 2.7029x; 1.5889x over previous
#include <cuda_runtime.h>
#include <cstdint>

#define NN 50000
#define EE 625000
#define FF 128
#define GG 64
#define GN_EPS 1e-5f
#define NBLK 196   // ceil(NN/256)
#define STR 36     // smem tile stride: bank = 4*row+k -> conflict-free fragments

// ---------------- scratch (static device globals; no allocs) ----------------
__device__ __align__(16) float d_deg[NN];
__device__ __align__(16) float d_dinv[NN];
__device__ __align__(16) int   d_cnt[NN];
__device__ __align__(16) int   d_rowptr[NN + 1];
__device__ __align__(16) int   d_cursor[NN];
__device__ __align__(16) int   d_bsum[256];
__device__ __align__(16) int   d_col[EE];
__device__ __align__(16) float d_val[EE];
__device__ __align__(16) float d_hbuf[3 * NN * FF];     // h1, h2, h3
__device__ __align__(16) float d_wt[4 * FF * FF];       // W^T per hop
__device__ __align__(16) float d_gmean[GG * FF];        // sum -> mean
__device__ __align__(16) float d_grvar[GG * FF];        // sumsq -> rsqrt(var+eps)
__device__ __align__(16) int   d_gstart[GG + 1];

__device__ __forceinline__ uint32_t f2tf32(float f) {
    uint32_t u;
    asm("cvt.rna.tf32.f32 %0, %1;" : "=r"(u) : "f"(f));
    return u;
}

__device__ __forceinline__ void mma_tf32(float* c, const uint32_t* a,
                                         const uint32_t* b) {
    asm volatile(
        "mma.sync.aligned.m16n8k8.row.col.f32.tf32.tf32.f32 "
        "{%0,%1,%2,%3}, {%4,%5,%6,%7}, {%8,%9}, {%0,%1,%2,%3};"
        : "+f"(c[0]), "+f"(c[1]), "+f"(c[2]), "+f"(c[3])
        : "r"(a[0]), "r"(a[1]), "r"(a[2]), "r"(a[3]), "r"(b[0]), "r"(b[1]));
}

// ---------------- fused init: zero deg/cnt, W^T, bounds, clear stat accum ----
__global__ void init_kernel(const float* __restrict__ tag_w,
                            const int* __restrict__ batch) {
    int i = blockIdx.x * 256 + threadIdx.x;    // 0..65535
    if (i < NN) { d_deg[i] = 0.f; d_cnt[i] = 0; }
    if (i < 4 * FF * FF) {
        int p = i >> 14, rem = i & 16383;
        int n = rem >> 7, k = rem & 127;
        d_wt[i] = tag_w[p * FF * FF + k * FF + n];
    }
    if (i < GG * FF) { d_gmean[i] = 0.f; d_grvar[i] = 0.f; }
    if (i < NN) {
        int b  = batch[i];
        int bp = (i == 0) ? -1 : batch[i - 1];
        for (int g = bp + 1; g <= b; ++g) d_gstart[g] = i;
        if (i == NN - 1)
            for (int g = b + 1; g <= GG; ++g) d_gstart[g] = NN;
    }
}

__global__ void deg_kernel(const int* __restrict__ ei,
                           const float* __restrict__ ew) {
    int e = blockIdx.x * blockDim.x + threadIdx.x;
    if (e >= EE) return;
    int dst = ei[EE + e];
    atomicAdd(&d_deg[dst], ew[e]);
    atomicAdd(&d_cnt[dst], 1);
}

__device__ __forceinline__ int warp_incl_scan(int v, int lane) {
    #pragma unroll
    for (int o = 1; o < 32; o <<= 1) {
        int t = __shfl_up_sync(0xFFFFFFFFu, v, o);
        if (lane >= o) v += t;
    }
    return v;
}

// block scan of d_cnt; also computes d_dinv (deg complete by now)
__global__ void scan_block_kernel() {
    __shared__ int ws[8];
    int t = threadIdx.x, b = blockIdx.x;
    int i = b * 256 + t;
    int lane = t & 31, wid = t >> 5;
    if (i < NN) {
        float d = d_deg[i];
        d_dinv[i] = (d > 0.f) ? rsqrtf(fmaxf(d, 1e-30f)) : 0.f;
    }
    int x = (i < NN) ? d_cnt[i] : 0;
    int v = warp_incl_scan(x, lane);
    if (lane == 31) ws[wid] = v;
    __syncthreads();
    if (t == 0) {
        int s = 0;
        #pragma unroll
        for (int k = 0; k < 8; ++k) { int tmp = ws[k]; ws[k] = s; s += tmp; }
    }
    __syncthreads();
    int excl = v - x + ws[wid];
    if (i < NN) d_rowptr[i] = excl;
    if (t == 255) d_bsum[b] = excl + x;
}

__global__ void scan_sums_kernel() {
    __shared__ int ws[8];
    int t = threadIdx.x;
    int lane = t & 31, wid = t >> 5;
    int x = (t < NBLK) ? d_bsum[t] : 0;
    int v = warp_incl_scan(x, lane);
    if (lane == 31) ws[wid] = v;
    __syncthreads();
    if (t == 0) {
        int s = 0;
        #pragma unroll
        for (int k = 0; k < 8; ++k) { int tmp = ws[k]; ws[k] = s; s += tmp; }
    }
    __syncthreads();
    int excl = v - x + ws[wid];
    if (t < NBLK) d_bsum[t] = excl;
    if (t == NBLK - 1) d_rowptr[NN] = excl + x;
}

__global__ void scan_add_kernel() {
    int i = blockIdx.x * 256 + threadIdx.x;
    if (i >= NN) return;
    int r = d_rowptr[i] + d_bsum[blockIdx.x];
    d_rowptr[i] = r;
    d_cursor[i] = r;
}

__global__ void fill_kernel(const int* __restrict__ ei,
                            const float* __restrict__ ew) {
    int e = blockIdx.x * blockDim.x + threadIdx.x;
    if (e >= EE) return;
    int s = ei[e];
    int d = ei[EE + e];
    float nv = d_dinv[s] * ew[e] * d_dinv[d];
    int p = atomicAdd(&d_cursor[d], 1);
    d_col[p] = s;
    d_val[p] = nv;
}

// ---------------- SpMM: one warp per destination row ----------------
__global__ void spmm_kernel(const float* __restrict__ y,
                            int in_idx, int out_idx) {
    const float* hin = (in_idx < 0) ? y : (d_hbuf + (size_t)in_idx * NN * FF);
    float* hout = d_hbuf + (size_t)out_idx * NN * FF;
    int warp = (blockIdx.x * blockDim.x + threadIdx.x) >> 5;
    if (warp >= NN) return;
    int lane = threadIdx.x & 31;
    int beg = d_rowptr[warp], end = d_rowptr[warp + 1];
    float4 acc = make_float4(0.f, 0.f, 0.f, 0.f);
    int e = beg;
    for (; e + 8 <= end; e += 8) {
        int c[8]; float v[8];
        #pragma unroll
        for (int u = 0; u < 8; ++u) { c[u] = d_col[e + u]; v[u] = d_val[e + u]; }
        float4 x[8];
        #pragma unroll
        for (int u = 0; u < 8; ++u)
            x[u] = *(const float4*)&hin[(size_t)c[u] * FF + lane * 4];
        #pragma unroll
        for (int u = 0; u < 8; ++u) {
            acc.x += v[u] * x[u].x;
            acc.y += v[u] * x[u].y;
            acc.z += v[u] * x[u].z;
            acc.w += v[u] * x[u].w;
        }
    }
    for (; e + 4 <= end; e += 4) {
        int   c0 = d_col[e],   c1 = d_col[e+1], c2 = d_col[e+2], c3 = d_col[e+3];
        float v0 = d_val[e],   v1 = d_val[e+1], v2 = d_val[e+2], v3 = d_val[e+3];
        float4 x0 = *(const float4*)&hin[(size_t)c0 * FF + lane * 4];
        float4 x1 = *(const float4*)&hin[(size_t)c1 * FF + lane * 4];
        float4 x2 = *(const float4*)&hin[(size_t)c2 * FF + lane * 4];
        float4 x3 = *(const float4*)&hin[(size_t)c3 * FF + lane * 4];
        acc.x += v0*x0.x + v1*x1.x + v2*x2.x + v3*x3.x;
        acc.y += v0*x0.y + v1*x1.y + v2*x2.y + v3*x3.y;
        acc.z += v0*x0.z + v1*x1.z + v2*x2.z + v3*x3.z;
        acc.w += v0*x0.w + v1*x1.w + v2*x2.w + v3*x3.w;
    }
    for (; e < end; ++e) {
        int c = d_col[e]; float v = d_val[e];
        float4 x = *(const float4*)&hin[(size_t)c * FF + lane * 4];
        acc.x += v*x.x; acc.y += v*x.y; acc.z += v*x.z; acc.w += v*x.w;
    }
    *(float4*)&hout[(size_t)warp * FF + lane * 4] = acc;
}

// ---------------- tf32 mma.sync GEMM (conflict-free STR=36 + reg prefetch) --
// out[N,128] = sum_{p=0..3} A_p[N,128] @ W_p[128,128] + b
__global__ __launch_bounds__(256) void gemm_mma_kernel(
        const float* __restrict__ y,
        const float* __restrict__ tag_b,
        float* __restrict__ out) {
    __shared__ uint32_t As[128 * STR];   // [row][k] tf32
    __shared__ uint32_t Bs[128 * STR];   // [n][k]  tf32 (W^T)

    int t = threadIdx.x;
    int wid = t >> 5, lane = t & 31;
    int gid = lane >> 2, tid4 = lane & 3;
    int block_row = blockIdx.x * 128;
    int rbase = (wid >> 1) * 32;         // warp row base (0,32,64,96)
    int cbase = (wid & 1) * 64;          // warp col base (0,64)

    float acc[2][8][4];
    #pragma unroll
    for (int m = 0; m < 2; ++m)
        #pragma unroll
        for (int c = 0; c < 8; ++c)
            #pragma unroll
            for (int j = 0; j < 4; ++j) acc[m][c][j] = 0.f;

    float4 pa[4], pb[4];
    auto ldchunk = [&](int chunk) {
        int p = chunk >> 2, kcc = chunk & 3;
        const float* Asrc = (p == 0) ? y : (d_hbuf + (size_t)(p - 1) * NN * FF);
        const float* Bsrc = d_wt + p * FF * FF;
        #pragma unroll
        for (int i = 0; i < 4; ++i) {
            int idx = i * 256 + t;        // 0..1023
            int r  = idx >> 3;            // 0..127
            int c4 = (idx & 7) * 4;       // 0..28
            int grow = block_row + r;
            pa[i] = (grow < NN)
                ? *(const float4*)&Asrc[(size_t)grow * FF + kcc * 32 + c4]
                : make_float4(0.f, 0.f, 0.f, 0.f);
            pb[i] = *(const float4*)&Bsrc[r * FF + kcc * 32 + c4];
        }
    };
    auto stchunk = [&]() {
        #pragma unroll
        for (int i = 0; i < 4; ++i) {
            int idx = i * 256 + t;
            int r  = idx >> 3;
            int c4 = (idx & 7) * 4;
            As[r * STR + c4 + 0] = f2tf32(pa[i].x);
            As[r * STR + c4 + 1] = f2tf32(pa[i].y);
            As[r * STR + c4 + 2] = f2tf32(pa[i].z);
            As[r * STR + c4 + 3] = f2tf32(pa[i].w);
            Bs[r * STR + c4 + 0] = f2tf32(pb[i].x);
            Bs[r * STR + c4 + 1] = f2tf32(pb[i].y);
            Bs[r * STR + c4 + 2] = f2tf32(pb[i].z);
            Bs[r * STR + c4 + 3] = f2tf32(pb[i].w);
        }
    };

    ldchunk(0);
    stchunk();
    __syncthreads();

    #pragma unroll 1
    for (int chunk = 0; chunk < 16; ++chunk) {
        if (chunk < 15) ldchunk(chunk + 1);   // overlap LDG with compute
        #pragma unroll
        for (int k0 = 0; k0 < 32; k0 += 8) {
            uint32_t a[2][4];
            #pragma unroll
            for (int m = 0; m < 2; ++m) {
                int row = rbase + m * 16 + gid;
                a[m][0] = As[row * STR + k0 + tid4];
                a[m][1] = As[(row + 8) * STR + k0 + tid4];
                a[m][2] = As[row * STR + k0 + tid4 + 4];
                a[m][3] = As[(row + 8) * STR + k0 + tid4 + 4];
            }
            uint32_t b[8][2];
            #pragma unroll
            for (int c = 0; c < 8; ++c) {
                int n = cbase + c * 8 + gid;
                b[c][0] = Bs[n * STR + k0 + tid4];
                b[c][1] = Bs[n * STR + k0 + tid4 + 4];
            }
            #pragma unroll
            for (int m = 0; m < 2; ++m)
                #pragma unroll
                for (int c = 0; c < 8; ++c)
                    mma_tf32(acc[m][c], a[m], b[c]);
        }
        __syncthreads();
        if (chunk < 15) {
            stchunk();
            __syncthreads();
        }
    }

    // epilogue: bias + store
    #pragma unroll
    for (int m = 0; m < 2; ++m) {
        int row0 = block_row + rbase + m * 16 + gid;
        #pragma unroll
        for (int c = 0; c < 8; ++c) {
            int col = cbase + c * 8 + 2 * tid4;
            float b0 = tag_b[col], b1 = tag_b[col + 1];
            if (row0 < NN) {
                float2 o = make_float2(acc[m][c][0] + b0, acc[m][c][1] + b1);
                *(float2*)&out[(size_t)row0 * FF + col] = o;
            }
            if (row0 + 8 < NN) {
                float2 o = make_float2(acc[m][c][2] + b0, acc[m][c][3] + b1);
                *(float2*)&out[(size_t)(row0 + 8) * FF + col] = o;
            }
        }
    }
}

// ---------------- GraphNorm stats: partial (256 blocks) + finalize ----------
__global__ void stats_partial_kernel(const float* __restrict__ out) {
    __shared__ float ssum[4][FF];
    __shared__ float ssq[4][FF];
    int g  = blockIdx.x >> 2;      // graph
    int q  = blockIdx.x & 3;       // quarter
    int f  = threadIdx.x & 127;
    int rr = threadIdx.x >> 7;     // 0..3
    int s0 = d_gstart[g], s1 = d_gstart[g + 1];
    float sum = 0.f, sq = 0.f;
    for (int n = s0 + q * 4 + rr; n < s1; n += 16) {
        float v = out[(size_t)n * FF + f];
        sum += v; sq += v * v;
    }
    ssum[rr][f] = sum; ssq[rr][f] = sq;
    __syncthreads();
    if (threadIdx.x < FF) {
        sum = ssum[0][f] + ssum[1][f] + ssum[2][f] + ssum[3][f];
        sq  = ssq[0][f]  + ssq[1][f]  + ssq[2][f]  + ssq[3][f];
        atomicAdd(&d_gmean[g * FF + f], sum);
        atomicAdd(&d_grvar[g * FF + f], sq);
    }
}

__global__ void stats_final_kernel(const float* __restrict__ gn_mean_scale) {
    int g = blockIdx.x, f = threadIdx.x;
    float cnt = (float)max(d_gstart[g + 1] - d_gstart[g], 1);
    float mean = d_gmean[g * FF + f] / cnt;
    float msq  = d_grvar[g * FF + f] / cnt;
    float sc = gn_mean_scale[f];
    float var = msq - 2.f * sc * mean * mean + sc * sc * mean * mean;
    d_gmean[g * FF + f] = mean;
    d_grvar[g * FF + f] = rsqrtf(var + GN_EPS);
}

// in-place: out = y + relu(gn_w * (out - s*mean) * rvar + gn_b)
__global__ void final_kernel(const float* __restrict__ y,
                             const int* __restrict__ batch,
                             const float* __restrict__ gn_weight,
                             const float* __restrict__ gn_bias,
                             const float* __restrict__ gn_mean_scale,
                             float* __restrict__ out) {
    int idx = blockIdx.x * blockDim.x + threadIdx.x;   // N*32
    if (idx >= NN * 32) return;
    int n = idx >> 5;
    int f = (idx & 31) * 4;
    int g = batch[n];
    float4 o = *(float4*)&out[(size_t)n * FF + f];
    float4 m = *(const float4*)&d_gmean[g * FF + f];
    float4 r = *(const float4*)&d_grvar[g * FF + f];
    float4 w = *(const float4*)&gn_weight[f];
    float4 b = *(const float4*)&gn_bias[f];
    float4 s = *(const float4*)&gn_mean_scale[f];
    float4 yy = *(const float4*)&y[(size_t)n * FF + f];
    float4 res;
    res.x = yy.x + fmaxf(w.x * (o.x - s.x * m.x) * r.x + b.x, 0.f);
    res.y = yy.y + fmaxf(w.y * (o.y - s.y * m.y) * r.y + b.y, 0.f);
    res.z = yy.z + fmaxf(w.z * (o.z - s.z * m.z) * r.z + b.z, 0.f);
    res.w = yy.w + fmaxf(w.w * (o.w - s.w * m.w) * r.w + b.w, 0.f);
    *(float4*)&out[(size_t)n * FF + f] = res;
}

// ---------------- launch ----------------
extern "C" void kernel_launch(void* const* d_in, const int* in_sizes, int n_in,
                              void* d_out, int out_size) {
    const float* y     = (const float*)d_in[0];
    const int*   ei    = (const int*)d_in[1];     // int32 (JAX x64-disabled)
    const float* ew    = (const float*)d_in[2];
    const int*   batch = (const int*)d_in[3];     // int32
    const float* tag_w = (const float*)d_in[4];
    const float* tag_b = (const float*)d_in[5];
    const float* gn_w  = (const float*)d_in[6];
    const float* gn_b  = (const float*)d_in[7];
    const float* gn_ms = (const float*)d_in[8];
    float* out = (float*)d_out;

    const int TB = 256;
    const int gE  = (EE + TB - 1) / TB;
    const int gW  = (NN * 32 + TB - 1) / TB;

    init_kernel<<<256, 256>>>(tag_w, batch);
    deg_kernel<<<gE, TB>>>(ei, ew);
    scan_block_kernel<<<NBLK, 256>>>();     // also computes dinv
    scan_sums_kernel<<<1, 256>>>();
    scan_add_kernel<<<NBLK, 256>>>();
    fill_kernel<<<gE, TB>>>(ei, ew);

    spmm_kernel<<<gW, TB>>>(y, -1, 0);   // y  -> h1
    spmm_kernel<<<gW, TB>>>(y,  0, 1);   // h1 -> h2
    spmm_kernel<<<gW, TB>>>(y,  1, 2);   // h2 -> h3

    gemm_mma_kernel<<<(NN + 127) / 128, 256>>>(y, tag_b, out);

    stats_partial_kernel<<<GG * 4, 512>>>(out);
    stats_final_kernel<<<GG, FF>>>(gn_ms);
    final_kernel<<<gW, TB>>>(y, batch, gn_w, gn_b, gn_ms, out);
}

// round 15
// speedup vs baseline: 2.7827x; 1.0295x over previous
#include <cuda_runtime.h>
#include <cuda_fp16.h>
#include <cstdint>

#define NN 50000
#define EE 625000
#define FF 128
#define GG 64
#define GN_EPS 1e-5f
#define NBLK 196   // ceil(NN/256)
#define STR 36     // smem tile stride: bank = 4*row+k -> conflict-free fragments

// ---------------- scratch (static device globals; no allocs) ----------------
__device__ __align__(16) float d_deg[NN];
__device__ __align__(16) float d_dinv[NN];
__device__ __align__(16) int   d_cnt[NN];
__device__ __align__(16) int   d_rowptr[NN + 1];
__device__ __align__(16) int   d_cursor[NN];
__device__ __align__(16) long long d_scan_pack[NBLK];   // {flag:32, value:32}
__device__ __align__(16) int   d_col[EE];
__device__ __align__(16) float d_val[EE];
__device__ __align__(16) __half d_h16[4 * NN * FF];     // y16, h1, h2, h3
__device__ __align__(16) float d_wt[4 * FF * FF];       // W^T per hop
__device__ __align__(16) float d_gmean[GG * FF];        // sum -> mean
__device__ __align__(16) float d_grvar[GG * FF];        // sumsq -> rsqrt(var+eps)
__device__ __align__(16) int   d_gstart[GG + 1];

__device__ __forceinline__ uint32_t f2tf32(float f) {
    uint32_t u;
    asm("cvt.rna.tf32.f32 %0, %1;" : "=r"(u) : "f"(f));
    return u;
}

__device__ __forceinline__ void mma_tf32(float* c, const uint32_t* a,
                                         const uint32_t* b) {
    asm volatile(
        "mma.sync.aligned.m16n8k8.row.col.f32.tf32.tf32.f32 "
        "{%0,%1,%2,%3}, {%4,%5,%6,%7}, {%8,%9}, {%0,%1,%2,%3};"
        : "+f"(c[0]), "+f"(c[1]), "+f"(c[2]), "+f"(c[3])
        : "r"(a[0]), "r"(a[1]), "r"(a[2]), "r"(a[3]), "r"(b[0]), "r"(b[1]));
}

// ---- fused init: zero deg/cnt/stats/flags, W^T, bounds, y->fp16 ----
__global__ void init_kernel(const float* __restrict__ y,
                            const float* __restrict__ tag_w,
                            const int* __restrict__ batch) {
    int i = blockIdx.x * 256 + threadIdx.x;
    if (i < NN) { d_deg[i] = 0.f; d_cnt[i] = 0; }
    if (i < NBLK) d_scan_pack[i] = 0;
    if (i == 0) d_rowptr[NN] = EE;
    if (i < 4 * FF * FF) {
        int p = i >> 14, rem = i & 16383;
        int n = rem >> 7, k = rem & 127;
        d_wt[i] = tag_w[p * FF * FF + k * FF + n];
    }
    if (i < GG * FF) { d_gmean[i] = 0.f; d_grvar[i] = 0.f; }
    if (i < NN) {
        int b  = batch[i];
        int bp = (i == 0) ? -1 : batch[i - 1];
        for (int g = bp + 1; g <= b; ++g) d_gstart[g] = i;
        if (i == NN - 1)
            for (int g = b + 1; g <= GG; ++g) d_gstart[g] = NN;
    }
    // y -> fp16 (slot 0): NN*FF/2 half2 elements
    if (i < NN * FF / 2) {
        float2 v = *(const float2*)&y[(size_t)i * 2];
        *((__half2*)d_h16 + i) = __floats2half2_rn(v.x, v.y);
    }
}

__global__ void deg_kernel(const int* __restrict__ ei,
                           const float* __restrict__ ew) {
    int e = blockIdx.x * blockDim.x + threadIdx.x;
    if (e >= EE) return;
    int dst = ei[EE + e];
    atomicAdd(&d_deg[dst], ew[e]);
    atomicAdd(&d_cnt[dst], 1);
}

__device__ __forceinline__ int warp_incl_scan(int v, int lane) {
    #pragma unroll
    for (int o = 1; o < 32; o <<= 1) {
        int t = __shfl_up_sync(0xFFFFFFFFu, v, o);
        if (lane >= o) v += t;
    }
    return v;
}

// single-pass scan with decoupled lookback; also computes dinv
__global__ void scan_fused_kernel() {
    __shared__ int ws[8];
    __shared__ int s_prefix;
    int t = threadIdx.x, b = blockIdx.x;
    int i = b * 256 + t;
    int lane = t & 31, wid = t >> 5;
    if (i < NN) {
        float d = d_deg[i];
        d_dinv[i] = (d > 0.f) ? rsqrtf(fmaxf(d, 1e-30f)) : 0.f;
    }
    int x = (i < NN) ? d_cnt[i] : 0;
    int v = warp_incl_scan(x, lane);
    if (lane == 31) ws[wid] = v;
    __syncthreads();
    if (t == 0) {
        int s = 0;
        #pragma unroll
        for (int k = 0; k < 8; ++k) { int tmp = ws[k]; ws[k] = s; s += tmp; }
        if (b == 0) {
            *(volatile long long*)&d_scan_pack[0] =
                ((long long)2 << 32) | (unsigned int)s;
            s_prefix = 0;
        } else {
            *(volatile long long*)&d_scan_pack[b] =
                ((long long)1 << 32) | (unsigned int)s;
            int pfx = 0;
            for (int j = b - 1; j >= 0; ) {
                long long pk;
                do { pk = *(volatile long long*)&d_scan_pack[j]; }
                while ((int)(pk >> 32) == 0);
                pfx += (int)(unsigned int)pk;
                if ((int)(pk >> 32) == 2) break;
                --j;
            }
            *(volatile long long*)&d_scan_pack[b] =
                ((long long)2 << 32) | (unsigned int)(pfx + s);
            s_prefix = pfx;
        }
    }
    __syncthreads();
    int excl = v - x + ws[wid] + s_prefix;
    if (i < NN) { d_rowptr[i] = excl; d_cursor[i] = excl; }
}

__global__ void fill_kernel(const int* __restrict__ ei,
                            const float* __restrict__ ew) {
    int e = blockIdx.x * blockDim.x + threadIdx.x;
    if (e >= EE) return;
    int s = ei[e];
    int d = ei[EE + e];
    float nv = d_dinv[s] * ew[e] * d_dinv[d];
    int p = atomicAdd(&d_cursor[d], 1);
    d_col[p] = s;
    d_val[p] = nv;
}

// ---------------- SpMM (fp16 in / fp16 out): one warp per dst row ----------
__global__ void spmm_kernel(int in_slot, int out_slot) {
    const __half* hin = d_h16 + (size_t)in_slot * NN * FF;
    __half* hout = d_h16 + (size_t)out_slot * NN * FF;
    int warp = (blockIdx.x * blockDim.x + threadIdx.x) >> 5;
    if (warp >= NN) return;
    int lane = threadIdx.x & 31;
    int beg = d_rowptr[warp], end = d_rowptr[warp + 1];
    float4 acc = make_float4(0.f, 0.f, 0.f, 0.f);
    int e = beg;
    for (; e + 8 <= end; e += 8) {
        int c[8]; float v[8];
        #pragma unroll
        for (int u = 0; u < 8; ++u) { c[u] = d_col[e + u]; v[u] = d_val[e + u]; }
        uint2 xr[8];
        #pragma unroll
        for (int u = 0; u < 8; ++u)
            xr[u] = *(const uint2*)(hin + (size_t)c[u] * FF + lane * 4);
        #pragma unroll
        for (int u = 0; u < 8; ++u) {
            float2 f01 = __half22float2(*(__half2*)&xr[u].x);
            float2 f23 = __half22float2(*(__half2*)&xr[u].y);
            acc.x += v[u] * f01.x; acc.y += v[u] * f01.y;
            acc.z += v[u] * f23.x; acc.w += v[u] * f23.y;
        }
    }
    for (; e < end; ++e) {
        int c = d_col[e]; float v = d_val[e];
        uint2 xr = *(const uint2*)(hin + (size_t)c * FF + lane * 4);
        float2 f01 = __half22float2(*(__half2*)&xr.x);
        float2 f23 = __half22float2(*(__half2*)&xr.y);
        acc.x += v * f01.x; acc.y += v * f01.y;
        acc.z += v * f23.x; acc.w += v * f23.y;
    }
    uint2 o;
    *(__half2*)&o.x = __floats2half2_rn(acc.x, acc.y);
    *(__half2*)&o.y = __floats2half2_rn(acc.z, acc.w);
    *(uint2*)(hout + (size_t)warp * FF + lane * 4) = o;
}

// ---------------- tf32 mma.sync GEMM ----------------
// out[N,128] = y@W0 + sum_{p=1..3} h_p@W_p + b ; h_p stored fp16
__global__ __launch_bounds__(256) void gemm_mma_kernel(
        const float* __restrict__ y,
        const float* __restrict__ tag_b,
        float* __restrict__ out) {
    __shared__ uint32_t As[128 * STR];
    __shared__ uint32_t Bs[128 * STR];

    int t = threadIdx.x;
    int wid = t >> 5, lane = t & 31;
    int gid = lane >> 2, tid4 = lane & 3;
    int block_row = blockIdx.x * 128;
    int rbase = (wid >> 1) * 32;
    int cbase = (wid & 1) * 64;

    float acc[2][8][4];
    #pragma unroll
    for (int m = 0; m < 2; ++m)
        #pragma unroll
        for (int c = 0; c < 8; ++c)
            #pragma unroll
            for (int j = 0; j < 4; ++j) acc[m][c][j] = 0.f;

    float4 pa[4], pb[4];
    auto ldchunk = [&](int chunk) {
        int p = chunk >> 2, kcc = chunk & 3;
        const float* Bsrc = d_wt + p * FF * FF;
        #pragma unroll
        for (int i = 0; i < 4; ++i) {
            int idx = i * 256 + t;
            int r  = idx >> 3;
            int c4 = (idx & 7) * 4;
            int grow = block_row + r;
            if (p == 0) {
                pa[i] = (grow < NN)
                    ? *(const float4*)&y[(size_t)grow * FF + kcc * 32 + c4]
                    : make_float4(0.f, 0.f, 0.f, 0.f);
            } else {
                if (grow < NN) {
                    uint2 h = *(const uint2*)(d_h16 + (size_t)p * NN * FF
                                              + (size_t)grow * FF + kcc * 32 + c4);
                    float2 f01 = __half22float2(*(__half2*)&h.x);
                    float2 f23 = __half22float2(*(__half2*)&h.y);
                    pa[i] = make_float4(f01.x, f01.y, f23.x, f23.y);
                } else {
                    pa[i] = make_float4(0.f, 0.f, 0.f, 0.f);
                }
            }
            pb[i] = *(const float4*)&Bsrc[r * FF + kcc * 32 + c4];
        }
    };
    auto stchunk = [&]() {
        #pragma unroll
        for (int i = 0; i < 4; ++i) {
            int idx = i * 256 + t;
            int r  = idx >> 3;
            int c4 = (idx & 7) * 4;
            As[r * STR + c4 + 0] = f2tf32(pa[i].x);
            As[r * STR + c4 + 1] = f2tf32(pa[i].y);
            As[r * STR + c4 + 2] = f2tf32(pa[i].z);
            As[r * STR + c4 + 3] = f2tf32(pa[i].w);
            Bs[r * STR + c4 + 0] = f2tf32(pb[i].x);
            Bs[r * STR + c4 + 1] = f2tf32(pb[i].y);
            Bs[r * STR + c4 + 2] = f2tf32(pb[i].z);
            Bs[r * STR + c4 + 3] = f2tf32(pb[i].w);
        }
    };

    ldchunk(0);
    stchunk();
    __syncthreads();

    #pragma unroll 1
    for (int chunk = 0; chunk < 16; ++chunk) {
        if (chunk < 15) ldchunk(chunk + 1);
        #pragma unroll
        for (int k0 = 0; k0 < 32; k0 += 8) {
            uint32_t a[2][4];
            #pragma unroll
            for (int m = 0; m < 2; ++m) {
                int row = rbase + m * 16 + gid;
                a[m][0] = As[row * STR + k0 + tid4];
                a[m][1] = As[(row + 8) * STR + k0 + tid4];
                a[m][2] = As[row * STR + k0 + tid4 + 4];
                a[m][3] = As[(row + 8) * STR + k0 + tid4 + 4];
            }
            uint32_t b[8][2];
            #pragma unroll
            for (int c = 0; c < 8; ++c) {
                int n = cbase + c * 8 + gid;
                b[c][0] = Bs[n * STR + k0 + tid4];
                b[c][1] = Bs[n * STR + k0 + tid4 + 4];
            }
            #pragma unroll
            for (int m = 0; m < 2; ++m)
                #pragma unroll
                for (int c = 0; c < 8; ++c)
                    mma_tf32(acc[m][c], a[m], b[c]);
        }
        __syncthreads();
        if (chunk < 15) {
            stchunk();
            __syncthreads();
        }
    }

    #pragma unroll
    for (int m = 0; m < 2; ++m) {
        int row0 = block_row + rbase + m * 16 + gid;
        #pragma unroll
        for (int c = 0; c < 8; ++c) {
            int col = cbase + c * 8 + 2 * tid4;
            float b0 = tag_b[col], b1 = tag_b[col + 1];
            if (row0 < NN) {
                float2 o = make_float2(acc[m][c][0] + b0, acc[m][c][1] + b1);
                *(float2*)&out[(size_t)row0 * FF + col] = o;
            }
            if (row0 + 8 < NN) {
                float2 o = make_float2(acc[m][c][2] + b0, acc[m][c][3] + b1);
                *(float2*)&out[(size_t)(row0 + 8) * FF + col] = o;
            }
        }
    }
}

// ---------------- GraphNorm stats: partial (256 blocks) + finalize ----------
__global__ void stats_partial_kernel(const float* __restrict__ out) {
    __shared__ float ssum[4][FF];
    __shared__ float ssq[4][FF];
    int g  = blockIdx.x >> 2;
    int q  = blockIdx.x & 3;
    int f  = threadIdx.x & 127;
    int rr = threadIdx.x >> 7;
    int s0 = d_gstart[g], s1 = d_gstart[g + 1];
    float sum = 0.f, sq = 0.f;
    for (int n = s0 + q * 4 + rr; n < s1; n += 16) {
        float v = out[(size_t)n * FF + f];
        sum += v; sq += v * v;
    }
    ssum[rr][f] = sum; ssq[rr][f] = sq;
    __syncthreads();
    if (threadIdx.x < FF) {
        sum = ssum[0][f] + ssum[1][f] + ssum[2][f] + ssum[3][f];
        sq  = ssq[0][f]  + ssq[1][f]  + ssq[2][f]  + ssq[3][f];
        atomicAdd(&d_gmean[g * FF + f], sum);
        atomicAdd(&d_grvar[g * FF + f], sq);
    }
}

__global__ void stats_final_kernel(const float* __restrict__ gn_mean_scale) {
    int g = blockIdx.x, f = threadIdx.x;
    float cnt = (float)max(d_gstart[g + 1] - d_gstart[g], 1);
    float mean = d_gmean[g * FF + f] / cnt;
    float msq  = d_grvar[g * FF + f] / cnt;
    float sc = gn_mean_scale[f];
    float var = msq - 2.f * sc * mean * mean + sc * sc * mean * mean;
    d_gmean[g * FF + f] = mean;
    d_grvar[g * FF + f] = rsqrtf(var + GN_EPS);
}

// in-place: out = y + relu(gn_w * (out - s*mean) * rvar + gn_b)
__global__ void final_kernel(const float* __restrict__ y,
                             const int* __restrict__ batch,
                             const float* __restrict__ gn_weight,
                             const float* __restrict__ gn_bias,
                             const float* __restrict__ gn_mean_scale,
                             float* __restrict__ out) {
    int idx = blockIdx.x * blockDim.x + threadIdx.x;
    if (idx >= NN * 32) return;
    int n = idx >> 5;
    int f = (idx & 31) * 4;
    int g = batch[n];
    float4 o = *(float4*)&out[(size_t)n * FF + f];
    float4 m = *(const float4*)&d_gmean[g * FF + f];
    float4 r = *(const float4*)&d_grvar[g * FF + f];
    float4 w = *(const float4*)&gn_weight[f];
    float4 b = *(const float4*)&gn_bias[f];
    float4 s = *(const float4*)&gn_mean_scale[f];
    float4 yy = *(const float4*)&y[(size_t)n * FF + f];
    float4 res;
    res.x = yy.x + fmaxf(w.x * (o.x - s.x * m.x) * r.x + b.x, 0.f);
    res.y = yy.y + fmaxf(w.y * (o.y - s.y * m.y) * r.y + b.y, 0.f);
    res.z = yy.z + fmaxf(w.z * (o.z - s.z * m.z) * r.z + b.z, 0.f);
    res.w = yy.w + fmaxf(w.w * (o.w - s.w * m.w) * r.w + b.w, 0.f);
    *(float4*)&out[(size_t)n * FF + f] = res;
}

// ---------------- launch ----------------
extern "C" void kernel_launch(void* const* d_in, const int* in_sizes, int n_in,
                              void* d_out, int out_size) {
    const float* y     = (const float*)d_in[0];
    const int*   ei    = (const int*)d_in[1];
    const float* ew    = (const float*)d_in[2];
    const int*   batch = (const int*)d_in[3];
    const float* tag_w = (const float*)d_in[4];
    const float* tag_b = (const float*)d_in[5];
    const float* gn_w  = (const float*)d_in[6];
    const float* gn_b  = (const float*)d_in[7];
    const float* gn_ms = (const float*)d_in[8];
    float* out = (float*)d_out;

    const int TB = 256;
    const int gE  = (EE + TB - 1) / TB;
    const int gW  = (NN * 32 + TB - 1) / TB;

    init_kernel<<<(NN * FF / 2 + 255) / 256, 256>>>(y, tag_w, batch);
    deg_kernel<<<gE, TB>>>(ei, ew);
    scan_fused_kernel<<<NBLK, 256>>>();
    fill_kernel<<<gE, TB>>>(ei, ew);

    spmm_kernel<<<gW, TB>>>(0, 1);   // y16 -> h1
    spmm_kernel<<<gW, TB>>>(1, 2);   // h1  -> h2
    spmm_kernel<<<gW, TB>>>(2, 3);   // h2  -> h3

    gemm_mma_kernel<<<(NN + 127) / 128, 256>>>(y, tag_b, out);

    stats_partial_kernel<<<GG * 4, 512>>>(out);
    stats_final_kernel<<<GG, FF>>>(gn_ms);
    final_kernel<<<gW, TB>>>(y, batch, gn_w, gn_b, gn_ms, out);
}

// round 16
// speedup vs baseline: 2.9290x; 1.0526x over previous
#include <cuda_runtime.h>
#include <cuda_fp16.h>
#include <cstdint>

#define NN 50000
#define EE 625000
#define FF 128
#define GG 64
#define GN_EPS 1e-5f
#define NBLK 196   // ceil(NN/256)
#define STR 36     // smem tile stride: bank = 4*row+k -> conflict-free fragments
#define GE 2442    // ceil(EE/256)
#define CONVBLK 6250  // NN*FF/4/256 conversion blocks (4 floats/thread)

// ---------------- scratch (static device globals; no allocs) ----------------
__device__ __align__(16) float d_deg[NN];
__device__ __align__(16) float d_dinv[NN];
__device__ __align__(16) int   d_cnt[NN];
__device__ __align__(16) int   d_rowptr[NN + 1];
__device__ __align__(16) int   d_cursor[NN];
__device__ __align__(16) long long d_scan_pack[NBLK];   // {flag:32, value:32}
__device__ __align__(16) long long d_colval[EE];        // {val':32hi, col:32lo}
__device__ __align__(16) __half d_h16[4 * NN * FF];     // y16, h1, h2, h3
__device__ __align__(16) float d_wt[4 * FF * FF];       // W^T per hop
__device__ __align__(16) float d_gmean[GG * FF];        // sum -> mean
__device__ __align__(16) float d_grvar[GG * FF];        // sumsq -> rsqrt(var+eps)
__device__ __align__(16) int   d_gstart[GG + 1];

__device__ __forceinline__ uint32_t f2tf32(float f) {
    uint32_t u;
    asm("cvt.rna.tf32.f32 %0, %1;" : "=r"(u) : "f"(f));
    return u;
}

__device__ __forceinline__ void mma_tf32(float* c, const uint32_t* a,
                                         const uint32_t* b) {
    asm volatile(
        "mma.sync.aligned.m16n8k8.row.col.f32.tf32.tf32.f32 "
        "{%0,%1,%2,%3}, {%4,%5,%6,%7}, {%8,%9}, {%0,%1,%2,%3};"
        : "+f"(c[0]), "+f"(c[1]), "+f"(c[2]), "+f"(c[3])
        : "r"(a[0]), "r"(a[1]), "r"(a[2]), "r"(a[3]), "r"(b[0]), "r"(b[1]));
}

// ---- small init: zeros, W^T, bounds (256 blocks) ----
__global__ void init_kernel(const float* __restrict__ tag_w,
                            const int* __restrict__ batch) {
    int i = blockIdx.x * 256 + threadIdx.x;    // 0..65535
    if (i < NN) { d_deg[i] = 0.f; d_cnt[i] = 0; }
    if (i < NBLK) d_scan_pack[i] = 0;
    if (i == 0) d_rowptr[NN] = EE;
    if (i < 4 * FF * FF) {
        int p = i >> 14, rem = i & 16383;
        int n = rem >> 7, k = rem & 127;
        d_wt[i] = tag_w[p * FF * FF + k * FF + n];
    }
    if (i < GG * FF) { d_gmean[i] = 0.f; d_grvar[i] = 0.f; }
    if (i < NN) {
        int b  = batch[i];
        int bp = (i == 0) ? -1 : batch[i - 1];
        for (int g = bp + 1; g <= b; ++g) d_gstart[g] = i;
        if (i == NN - 1)
            for (int g = b + 1; g <= GG; ++g) d_gstart[g] = NN;
    }
}

__global__ void deg_kernel(const int* __restrict__ ei,
                           const float* __restrict__ ew) {
    int e = blockIdx.x * blockDim.x + threadIdx.x;
    if (e >= EE) return;
    int dst = ei[EE + e];
    atomicAdd(&d_deg[dst], ew[e]);
    atomicAdd(&d_cnt[dst], 1);
}

__device__ __forceinline__ int warp_incl_scan(int v, int lane) {
    #pragma unroll
    for (int o = 1; o < 32; o <<= 1) {
        int t = __shfl_up_sync(0xFFFFFFFFu, v, o);
        if (lane >= o) v += t;
    }
    return v;
}

// single-pass scan with decoupled lookback; also computes dinv
__global__ void scan_fused_kernel() {
    __shared__ int ws[8];
    __shared__ int s_prefix;
    int t = threadIdx.x, b = blockIdx.x;
    int i = b * 256 + t;
    int lane = t & 31, wid = t >> 5;
    if (i < NN) {
        float d = d_deg[i];
        d_dinv[i] = (d > 0.f) ? rsqrtf(fmaxf(d, 1e-30f)) : 0.f;
    }
    int x = (i < NN) ? d_cnt[i] : 0;
    int v = warp_incl_scan(x, lane);
    if (lane == 31) ws[wid] = v;
    __syncthreads();
    if (t == 0) {
        int s = 0;
        #pragma unroll
        for (int k = 0; k < 8; ++k) { int tmp = ws[k]; ws[k] = s; s += tmp; }
        if (b == 0) {
            *(volatile long long*)&d_scan_pack[0] =
                ((long long)2 << 32) | (unsigned int)s;
            s_prefix = 0;
        } else {
            *(volatile long long*)&d_scan_pack[b] =
                ((long long)1 << 32) | (unsigned int)s;
            int pfx = 0;
            for (int j = b - 1; j >= 0; ) {
                long long pk;
                do { pk = *(volatile long long*)&d_scan_pack[j]; }
                while ((int)(pk >> 32) == 0);
                pfx += (int)(unsigned int)pk;
                if ((int)(pk >> 32) == 2) break;
                --j;
            }
            *(volatile long long*)&d_scan_pack[b] =
                ((long long)2 << 32) | (unsigned int)(pfx + s);
            s_prefix = pfx;
        }
    }
    __syncthreads();
    int excl = v - x + ws[wid] + s_prefix;
    if (i < NN) { d_rowptr[i] = excl; d_cursor[i] = excl; }
}

// edges -> packed CSR {col, val'=ew*dinv[src]}; tail blocks: y -> fp16
__global__ void fill_kernel(const int* __restrict__ ei,
                            const float* __restrict__ ew,
                            const float* __restrict__ y) {
    int b = blockIdx.x;
    if (b < GE) {
        int e = b * 256 + threadIdx.x;
        if (e >= EE) return;
        int s = ei[e];
        int d = ei[EE + e];
        float nv = d_dinv[s] * ew[e];           // dinv[dst] folded into spmm
        int p = atomicAdd(&d_cursor[d], 1);
        long long pack = ((long long)__float_as_int(nv) << 32)
                       | (unsigned int)s;
        d_colval[p] = pack;
    } else {
        // y -> fp16 (slot 0): 4 floats per thread
        int i = (b - GE) * 256 + threadIdx.x;   // < NN*FF/4
        float4 v = *(const float4*)&y[(size_t)i * 4];
        uint2 o;
        *(__half2*)&o.x = __floats2half2_rn(v.x, v.y);
        *(__half2*)&o.y = __floats2half2_rn(v.z, v.w);
        *((uint2*)d_h16 + i) = o;
    }
}

// ---------------- SpMM (fp16): one warp per dst row; scale by dinv[row] ----
__global__ void spmm_kernel(int in_slot, int out_slot) {
    const __half* hin = d_h16 + (size_t)in_slot * NN * FF;
    __half* hout = d_h16 + (size_t)out_slot * NN * FF;
    int warp = (blockIdx.x * blockDim.x + threadIdx.x) >> 5;
    if (warp >= NN) return;
    int lane = threadIdx.x & 31;
    int beg = d_rowptr[warp], end = d_rowptr[warp + 1];
    float4 acc = make_float4(0.f, 0.f, 0.f, 0.f);
    int e = beg;
    for (; e + 8 <= end; e += 8) {
        long long cv[8];
        #pragma unroll
        for (int u = 0; u < 8; ++u) cv[u] = d_colval[e + u];
        uint2 xr[8];
        #pragma unroll
        for (int u = 0; u < 8; ++u) {
            int c = (int)(unsigned int)cv[u];
            xr[u] = *(const uint2*)(hin + (size_t)c * FF + lane * 4);
        }
        #pragma unroll
        for (int u = 0; u < 8; ++u) {
            float v = __int_as_float((int)(cv[u] >> 32));
            float2 f01 = __half22float2(*(__half2*)&xr[u].x);
            float2 f23 = __half22float2(*(__half2*)&xr[u].y);
            acc.x += v * f01.x; acc.y += v * f01.y;
            acc.z += v * f23.x; acc.w += v * f23.y;
        }
    }
    for (; e < end; ++e) {
        long long cv = d_colval[e];
        int c = (int)(unsigned int)cv;
        float v = __int_as_float((int)(cv >> 32));
        uint2 xr = *(const uint2*)(hin + (size_t)c * FF + lane * 4);
        float2 f01 = __half22float2(*(__half2*)&xr.x);
        float2 f23 = __half22float2(*(__half2*)&xr.y);
        acc.x += v * f01.x; acc.y += v * f01.y;
        acc.z += v * f23.x; acc.w += v * f23.y;
    }
    float dr = d_dinv[warp];
    uint2 o;
    *(__half2*)&o.x = __floats2half2_rn(acc.x * dr, acc.y * dr);
    *(__half2*)&o.y = __floats2half2_rn(acc.z * dr, acc.w * dr);
    *(uint2*)(hout + (size_t)warp * FF + lane * 4) = o;
}

// ---------------- tf32 mma.sync GEMM ----------------
// out[N,128] = y@W0 + sum_{p=1..3} h_p@W_p + b ; h_p stored fp16
__global__ __launch_bounds__(256) void gemm_mma_kernel(
        const float* __restrict__ y,
        const float* __restrict__ tag_b,
        float* __restrict__ out) {
    __shared__ uint32_t As[128 * STR];
    __shared__ uint32_t Bs[128 * STR];

    int t = threadIdx.x;
    int wid = t >> 5, lane = t & 31;
    int gid = lane >> 2, tid4 = lane & 3;
    int block_row = blockIdx.x * 128;
    int rbase = (wid >> 1) * 32;
    int cbase = (wid & 1) * 64;

    float acc[2][8][4];
    #pragma unroll
    for (int m = 0; m < 2; ++m)
        #pragma unroll
        for (int c = 0; c < 8; ++c)
            #pragma unroll
            for (int j = 0; j < 4; ++j) acc[m][c][j] = 0.f;

    float4 pa[4], pb[4];
    auto ldchunk = [&](int chunk) {
        int p = chunk >> 2, kcc = chunk & 3;
        const float* Bsrc = d_wt + p * FF * FF;
        #pragma unroll
        for (int i = 0; i < 4; ++i) {
            int idx = i * 256 + t;
            int r  = idx >> 3;
            int c4 = (idx & 7) * 4;
            int grow = block_row + r;
            if (p == 0) {
                pa[i] = (grow < NN)
                    ? *(const float4*)&y[(size_t)grow * FF + kcc * 32 + c4]
                    : make_float4(0.f, 0.f, 0.f, 0.f);
            } else {
                if (grow < NN) {
                    uint2 h = *(const uint2*)(d_h16 + (size_t)p * NN * FF
                                              + (size_t)grow * FF + kcc * 32 + c4);
                    float2 f01 = __half22float2(*(__half2*)&h.x);
                    float2 f23 = __half22float2(*(__half2*)&h.y);
                    pa[i] = make_float4(f01.x, f01.y, f23.x, f23.y);
                } else {
                    pa[i] = make_float4(0.f, 0.f, 0.f, 0.f);
                }
            }
            pb[i] = *(const float4*)&Bsrc[r * FF + kcc * 32 + c4];
        }
    };
    auto stchunk = [&]() {
        #pragma unroll
        for (int i = 0; i < 4; ++i) {
            int idx = i * 256 + t;
            int r  = idx >> 3;
            int c4 = (idx & 7) * 4;
            As[r * STR + c4 + 0] = f2tf32(pa[i].x);
            As[r * STR + c4 + 1] = f2tf32(pa[i].y);
            As[r * STR + c4 + 2] = f2tf32(pa[i].z);
            As[r * STR + c4 + 3] = f2tf32(pa[i].w);
            Bs[r * STR + c4 + 0] = f2tf32(pb[i].x);
            Bs[r * STR + c4 + 1] = f2tf32(pb[i].y);
            Bs[r * STR + c4 + 2] = f2tf32(pb[i].z);
            Bs[r * STR + c4 + 3] = f2tf32(pb[i].w);
        }
    };

    ldchunk(0);
    stchunk();
    __syncthreads();

    #pragma unroll 1
    for (int chunk = 0; chunk < 16; ++chunk) {
        if (chunk < 15) ldchunk(chunk + 1);
        #pragma unroll
        for (int k0 = 0; k0 < 32; k0 += 8) {
            uint32_t a[2][4];
            #pragma unroll
            for (int m = 0; m < 2; ++m) {
                int row = rbase + m * 16 + gid;
                a[m][0] = As[row * STR + k0 + tid4];
                a[m][1] = As[(row + 8) * STR + k0 + tid4];
                a[m][2] = As[row * STR + k0 + tid4 + 4];
                a[m][3] = As[(row + 8) * STR + k0 + tid4 + 4];
            }
            uint32_t b[8][2];
            #pragma unroll
            for (int c = 0; c < 8; ++c) {
                int n = cbase + c * 8 + gid;
                b[c][0] = Bs[n * STR + k0 + tid4];
                b[c][1] = Bs[n * STR + k0 + tid4 + 4];
            }
            #pragma unroll
            for (int m = 0; m < 2; ++m)
                #pragma unroll
                for (int c = 0; c < 8; ++c)
                    mma_tf32(acc[m][c], a[m], b[c]);
        }
        __syncthreads();
        if (chunk < 15) {
            stchunk();
            __syncthreads();
        }
    }

    #pragma unroll
    for (int m = 0; m < 2; ++m) {
        int row0 = block_row + rbase + m * 16 + gid;
        #pragma unroll
        for (int c = 0; c < 8; ++c) {
            int col = cbase + c * 8 + 2 * tid4;
            float b0 = tag_b[col], b1 = tag_b[col + 1];
            if (row0 < NN) {
                float2 o = make_float2(acc[m][c][0] + b0, acc[m][c][1] + b1);
                *(float2*)&out[(size_t)row0 * FF + col] = o;
            }
            if (row0 + 8 < NN) {
                float2 o = make_float2(acc[m][c][2] + b0, acc[m][c][3] + b1);
                *(float2*)&out[(size_t)(row0 + 8) * FF + col] = o;
            }
        }
    }
}

// ---------------- GraphNorm stats: partial (256 blocks) + finalize ----------
__global__ void stats_partial_kernel(const float* __restrict__ out) {
    __shared__ float ssum[4][FF];
    __shared__ float ssq[4][FF];
    int g  = blockIdx.x >> 2;
    int q  = blockIdx.x & 3;
    int f  = threadIdx.x & 127;
    int rr = threadIdx.x >> 7;
    int s0 = d_gstart[g], s1 = d_gstart[g + 1];
    float sum = 0.f, sq = 0.f;
    for (int n = s0 + q * 4 + rr; n < s1; n += 16) {
        float v = out[(size_t)n * FF + f];
        sum += v; sq += v * v;
    }
    ssum[rr][f] = sum; ssq[rr][f] = sq;
    __syncthreads();
    if (threadIdx.x < FF) {
        sum = ssum[0][f] + ssum[1][f] + ssum[2][f] + ssum[3][f];
        sq  = ssq[0][f]  + ssq[1][f]  + ssq[2][f]  + ssq[3][f];
        atomicAdd(&d_gmean[g * FF + f], sum);
        atomicAdd(&d_grvar[g * FF + f], sq);
    }
}

__global__ void stats_final_kernel(const float* __restrict__ gn_mean_scale) {
    int g = blockIdx.x, f = threadIdx.x;
    float cnt = (float)max(d_gstart[g + 1] - d_gstart[g], 1);
    float mean = d_gmean[g * FF + f] / cnt;
    float msq  = d_grvar[g * FF + f] / cnt;
    float sc = gn_mean_scale[f];
    float var = msq - 2.f * sc * mean * mean + sc * sc * mean * mean;
    d_gmean[g * FF + f] = mean;
    d_grvar[g * FF + f] = rsqrtf(var + GN_EPS);
}

// in-place: out = y + relu(gn_w * (out - s*mean) * rvar + gn_b)
__global__ void final_kernel(const float* __restrict__ y,
                             const int* __restrict__ batch,
                             const float* __restrict__ gn_weight,
                             const float* __restrict__ gn_bias,
                             const float* __restrict__ gn_mean_scale,
                             float* __restrict__ out) {
    int idx = blockIdx.x * blockDim.x + threadIdx.x;
    if (idx >= NN * 32) return;
    int n = idx >> 5;
    int f = (idx & 31) * 4;
    int g = batch[n];
    float4 o = *(float4*)&out[(size_t)n * FF + f];
    float4 m = *(const float4*)&d_gmean[g * FF + f];
    float4 r = *(const float4*)&d_grvar[g * FF + f];
    float4 w = *(const float4*)&gn_weight[f];
    float4 b = *(const float4*)&gn_bias[f];
    float4 s = *(const float4*)&gn_mean_scale[f];
    float4 yy = *(const float4*)&y[(size_t)n * FF + f];
    float4 res;
    res.x = yy.x + fmaxf(w.x * (o.x - s.x * m.x) * r.x + b.x, 0.f);
    res.y = yy.y + fmaxf(w.y * (o.y - s.y * m.y) * r.y + b.y, 0.f);
    res.z = yy.z + fmaxf(w.z * (o.z - s.z * m.z) * r.z + b.z, 0.f);
    res.w = yy.w + fmaxf(w.w * (o.w - s.w * m.w) * r.w + b.w, 0.f);
    *(float4*)&out[(size_t)n * FF + f] = res;
}

// ---------------- launch ----------------
extern "C" void kernel_launch(void* const* d_in, const int* in_sizes, int n_in,
                              void* d_out, int out_size) {
    const float* y     = (const float*)d_in[0];
    const int*   ei    = (const int*)d_in[1];
    const float* ew    = (const float*)d_in[2];
    const int*   batch = (const int*)d_in[3];
    const float* tag_w = (const float*)d_in[4];
    const float* tag_b = (const float*)d_in[5];
    const float* gn_w  = (const float*)d_in[6];
    const float* gn_b  = (const float*)d_in[7];
    const float* gn_ms = (const float*)d_in[8];
    float* out = (float*)d_out;

    const int TB = 256;
    const int gW  = (NN * 32 + TB - 1) / TB;

    init_kernel<<<256, 256>>>(tag_w, batch);
    deg_kernel<<<GE, TB>>>(ei, ew);
    scan_fused_kernel<<<NBLK, 256>>>();
    fill_kernel<<<GE + CONVBLK, TB>>>(ei, ew, y);   // edges + y->fp16

    spmm_kernel<<<gW, TB>>>(0, 1);   // y16 -> h1
    spmm_kernel<<<gW, TB>>>(1, 2);   // h1  -> h2
    spmm_kernel<<<gW, TB>>>(2, 3);   // h2  -> h3

    gemm_mma_kernel<<<(NN + 127) / 128, 256>>>(y, tag_b, out);

    stats_partial_kernel<<<GG * 4, 512>>>(out);
    stats_final_kernel<<<GG, FF>>>(gn_ms);
    final_kernel<<<gW, TB>>>(y, batch, gn_w, gn_b, gn_ms, out);
}